// round 1
// baseline (speedup 1.0000x reference)
#include <cuda_runtime.h>
#include <math.h>

// Problem constants
#define BB 2
#define SS 2048
#define DD 1024
#define NH 16
#define HD 64
#define MR (BB*SS)      // 4096 rows
#define DHID (DD/4)     // 256

// Scratch (device globals; no allocation allowed)
__device__ float g_Q[MR*DD];
__device__ float g_K[MR*DD];
__device__ float g_V[MR*DD];
__device__ float g_A[MR*DD];
__device__ float g_Hd[MR*DHID];
__device__ float g_Mod[MR*DD];
__device__ float g_Z[MR*DD];

// ---------------------------------------------------------------------------
// C[M,N] = A[M,K] @ B[N,K]^T + bias[N], optional ReLU.
// BM=128, BN=64, BK=16, 256 threads, 8x4 per-thread microtile.
// M,N,K are multiples of the tile sizes for all calls here.
// ---------------------------------------------------------------------------
template<bool RELU>
__global__ __launch_bounds__(256)
void gemm_tn(const float* __restrict__ A, const float* __restrict__ B,
             const float* __restrict__ bias, float* __restrict__ C,
             int M, int N, int K)
{
    const int BM = 128, BN = 64, BK = 16;
    __shared__ __align__(16) float As[BK][BM + 4];
    __shared__ __align__(16) float Bs[BK][BN + 4];

    const int tid = threadIdx.x;
    const int bm = blockIdx.y * BM;
    const int bn = blockIdx.x * BN;
    const int ty = tid >> 4;     // 0..15  -> 8 rows each
    const int tx = tid & 15;     // 0..15  -> 4 cols each

    float c[8][4];
#pragma unroll
    for (int i = 0; i < 8; i++)
#pragma unroll
        for (int j = 0; j < 4; j++) c[i][j] = 0.f;

    const float* Ag = A + (size_t)bm * K;
    const float* Bg = B + (size_t)bn * K;

    for (int k0 = 0; k0 < K; k0 += BK) {
        // Load A tile: 128 x 16 = 512 float4, 2 per thread
#pragma unroll
        for (int i = 0; i < 2; i++) {
            int idx = tid + i * 256;          // 0..511
            int m   = idx >> 2;               // 0..127
            int k4  = idx & 3;                // 0..3
            float4 v = *(const float4*)(Ag + (size_t)m * K + k0 + k4 * 4);
            As[k4*4+0][m] = v.x;
            As[k4*4+1][m] = v.y;
            As[k4*4+2][m] = v.z;
            As[k4*4+3][m] = v.w;
        }
        // Load B tile: 64 x 16 = 256 float4, 1 per thread
        {
            int n  = tid >> 2;                // 0..63
            int k4 = tid & 3;                 // 0..3
            float4 v = *(const float4*)(Bg + (size_t)n * K + k0 + k4 * 4);
            Bs[k4*4+0][n] = v.x;
            Bs[k4*4+1][n] = v.y;
            Bs[k4*4+2][n] = v.z;
            Bs[k4*4+3][n] = v.w;
        }
        __syncthreads();

#pragma unroll
        for (int kk = 0; kk < BK; kk++) {
            float4 a0 = *(const float4*)&As[kk][ty * 8];
            float4 a1 = *(const float4*)&As[kk][ty * 8 + 4];
            float4 b0 = *(const float4*)&Bs[kk][tx * 4];
            float a[8] = {a0.x, a0.y, a0.z, a0.w, a1.x, a1.y, a1.z, a1.w};
            float bv[4] = {b0.x, b0.y, b0.z, b0.w};
#pragma unroll
            for (int i = 0; i < 8; i++)
#pragma unroll
                for (int j = 0; j < 4; j++)
                    c[i][j] = fmaf(a[i], bv[j], c[i][j]);
        }
        __syncthreads();
    }

    // Epilogue: bias (+ ReLU), float4 stores
    float4 bia = *(const float4*)(bias + bn + tx * 4);
#pragma unroll
    for (int i = 0; i < 8; i++) {
        int mrow = bm + ty * 8 + i;
        float4 v;
        v.x = c[i][0] + bia.x;
        v.y = c[i][1] + bia.y;
        v.z = c[i][2] + bia.z;
        v.w = c[i][3] + bia.w;
        if (RELU) {
            v.x = fmaxf(v.x, 0.f); v.y = fmaxf(v.y, 0.f);
            v.z = fmaxf(v.z, 0.f); v.w = fmaxf(v.w, 0.f);
        }
        *(float4*)(C + (size_t)mrow * N + bn + tx * 4) = v;
    }
}

// ---------------------------------------------------------------------------
// Flash-attention (fp32): one thread = one query row, q & o accumulator in
// registers, K/V tiles (32 rows) staged in smem and read via broadcast LDS.
// Online softmax with per-tile max. Output written in merged [b,s,d] layout.
// grid: (S/128, H, B), block: 128
// ---------------------------------------------------------------------------
__global__ __launch_bounds__(128)
void attn_kernel(const float* __restrict__ Q, const float* __restrict__ Km,
                 const float* __restrict__ Vm, float* __restrict__ O)
{
    const int KT = 32;
    __shared__ __align__(16) float ks[KT][HD];
    __shared__ __align__(16) float vs[KT][HD];

    const int h = blockIdx.y;
    const int b = blockIdx.z;
    const int row = blockIdx.x * 128 + threadIdx.x;
    const float scale = 0.125f;  // 1/sqrt(64)

    const size_t base = ((size_t)b * SS + row) * DD + h * HD;

    float q[HD];
#pragma unroll
    for (int i = 0; i < HD / 4; i++) {
        float4 t = *(const float4*)(Q + base + i * 4);
        q[i*4+0] = t.x * scale; q[i*4+1] = t.y * scale;
        q[i*4+2] = t.z * scale; q[i*4+3] = t.w * scale;
    }

    float o[HD];
#pragma unroll
    for (int j = 0; j < HD; j++) o[j] = 0.f;
    float m = -1e30f, l = 0.f;

    const float* Kb = Km + (size_t)b * SS * DD + h * HD;
    const float* Vb = Vm + (size_t)b * SS * DD + h * HD;

    for (int k0 = 0; k0 < SS; k0 += KT) {
        // stage K/V tiles: 32 rows x 16 float4 = 512 f4 each; 4 per thread
#pragma unroll
        for (int i = 0; i < 4; i++) {
            int idx = threadIdx.x + i * 128;  // 0..511
            int kr  = idx >> 4;               // 0..31
            int c4  = idx & 15;               // 0..15
            *(float4*)&ks[kr][c4*4] = *(const float4*)(Kb + (size_t)(k0+kr) * DD + c4*4);
            *(float4*)&vs[kr][c4*4] = *(const float4*)(Vb + (size_t)(k0+kr) * DD + c4*4);
        }
        __syncthreads();

        float sc[KT];
        float tmax = -1e30f;
#pragma unroll
        for (int kr = 0; kr < KT; kr++) {
            float a0 = 0.f, a1 = 0.f, a2 = 0.f, a3 = 0.f;
            const float* kk = ks[kr];
#pragma unroll
            for (int c = 0; c < HD; c += 4) {
                a0 = fmaf(q[c+0], kk[c+0], a0);
                a1 = fmaf(q[c+1], kk[c+1], a1);
                a2 = fmaf(q[c+2], kk[c+2], a2);
                a3 = fmaf(q[c+3], kk[c+3], a3);
            }
            float s = (a0 + a1) + (a2 + a3);
            sc[kr] = s;
            tmax = fmaxf(tmax, s);
        }

        if (tmax > m) {
            float alpha = __expf(m - tmax);
            l *= alpha;
#pragma unroll
            for (int j = 0; j < HD; j++) o[j] *= alpha;
            m = tmax;
        }

#pragma unroll
        for (int kr = 0; kr < KT; kr++) {
            float p = __expf(sc[kr] - m);
            l += p;
            const float* vv = vs[kr];
#pragma unroll
            for (int j = 0; j < HD; j++) o[j] = fmaf(p, vv[j], o[j]);
        }
        __syncthreads();
    }

    float inv = 1.f / l;
    float* Op = O + base;
#pragma unroll
    for (int i = 0; i < HD / 4; i++) {
        float4 t;
        t.x = o[i*4+0] * inv; t.y = o[i*4+1] * inv;
        t.z = o[i*4+2] * inv; t.w = o[i*4+3] * inv;
        *(float4*)(Op + i * 4) = t;
    }
}

// ---------------------------------------------------------------------------
// Z = (A*attention_scale + attention_bias) * (1 + Mod*gate), gate from 4 scalars
// ---------------------------------------------------------------------------
__global__ void fuse_kernel(const float4* __restrict__ A, const float4* __restrict__ Mod,
                            float4* __restrict__ Z,
                            const float* __restrict__ dop, const float* __restrict__ ser,
                            const float* __restrict__ nor, const float* __restrict__ ace,
                            const float* __restrict__ asc, const float* __restrict__ abi,
                            int n4)
{
    int i = blockIdx.x * blockDim.x + threadIdx.x;
    if (i >= n4) return;
    float gate = 0.25f * (dop[0] + ser[0] + nor[0] + ace[0]);
    float s = asc[0], bb = abi[0];
    float4 a = A[i], md = Mod[i], z;
    z.x = (a.x * s + bb) * (1.f + md.x * gate);
    z.y = (a.y * s + bb) * (1.f + md.y * gate);
    z.z = (a.z * s + bb) * (1.f + md.z * gate);
    z.w = (a.w * s + bb) * (1.f + md.w * gate);
    Z[i] = z;
}

// ---------------------------------------------------------------------------
extern "C" void kernel_launch(void* const* d_in, const int* in_sizes, int n_in,
                              void* d_out, int out_size)
{
    const float* query = (const float*)d_in[0];
    const float* Wq  = (const float*)d_in[1];  const float* bq  = (const float*)d_in[2];
    const float* Wk  = (const float*)d_in[3];  const float* bk  = (const float*)d_in[4];
    const float* Wv  = (const float*)d_in[5];  const float* bv  = (const float*)d_in[6];
    const float* Wo  = (const float*)d_in[7];  const float* bo  = (const float*)d_in[8];
    const float* Wm1 = (const float*)d_in[9];  const float* bm1 = (const float*)d_in[10];
    const float* Wm2 = (const float*)d_in[11]; const float* bm2 = (const float*)d_in[12];
    const float* dop = (const float*)d_in[13];
    const float* ser = (const float*)d_in[14];
    const float* nor = (const float*)d_in[15];
    const float* ace = (const float*)d_in[16];
    const float* asc = (const float*)d_in[17];
    const float* abi = (const float*)d_in[18];
    float* out = (float*)d_out;

    float *Qp, *Kp, *Vp, *Ap, *Hp, *Mp, *Zp;
    cudaGetSymbolAddress((void**)&Qp, g_Q);
    cudaGetSymbolAddress((void**)&Kp, g_K);
    cudaGetSymbolAddress((void**)&Vp, g_V);
    cudaGetSymbolAddress((void**)&Ap, g_A);
    cudaGetSymbolAddress((void**)&Hp, g_Hd);
    cudaGetSymbolAddress((void**)&Mp, g_Mod);
    cudaGetSymbolAddress((void**)&Zp, g_Z);

    dim3 gBig(DD / 64, MR / 128);    // N=1024 GEMMs
    dim3 gHid(DHID / 64, MR / 128);  // N=256 GEMM

    // QKV projections
    gemm_tn<false><<<gBig, 256>>>(query, Wq, bq, Qp, MR, DD, DD);
    gemm_tn<false><<<gBig, 256>>>(query, Wk, bk, Kp, MR, DD, DD);
    gemm_tn<false><<<gBig, 256>>>(query, Wv, bv, Vp, MR, DD, DD);

    // Neuromodulation MLP
    gemm_tn<true ><<<gHid, 256>>>(query, Wm1, bm1, Hp, MR, DHID, DD);
    gemm_tn<false><<<gBig, 256>>>(Hp, Wm2, bm2, Mp, MR, DD, DHID);

    // Attention (writes merged [b,s,d])
    attn_kernel<<<dim3(SS / 128, NH, BB), 128>>>(Qp, Kp, Vp, Ap);

    // Gate fuse
    int n4 = MR * DD / 4;
    fuse_kernel<<<(n4 + 255) / 256, 256>>>((const float4*)Ap, (const float4*)Mp,
                                           (float4*)Zp, dop, ser, nor, ace, asc, abi, n4);

    // Output projection
    gemm_tn<false><<<gBig, 256>>>(Zp, Wo, bo, out, MR, DD, DD);
}

// round 3
// speedup vs baseline: 1.5904x; 1.5904x over previous
#include <cuda_runtime.h>
#include <cstdint>
#include <math.h>

// Problem constants
#define BB 2
#define SS 2048
#define DD 1024
#define NH 16
#define HD 64
#define MR (BB*SS)      // 4096 rows
#define DHID (DD/4)     // 256

// Scratch (device globals; no allocation allowed)
__device__ float g_Q[MR*DD];
__device__ float g_K[MR*DD];
__device__ float g_V[MR*DD];
__device__ float g_A[MR*DD];
__device__ float g_Hd[MR*DHID];
__device__ float g_Mod[MR*DD];
__device__ float g_Z[MR*DD];

// ===========================================================================
// f32x2 packed math (Blackwell, base-arch PTX)
// ===========================================================================
__device__ __forceinline__ unsigned long long pk2(float x, float y) {
    unsigned long long r;
    asm("mov.b64 %0, {%1, %2};" : "=l"(r) : "f"(x), "f"(y));
    return r;
}
__device__ __forceinline__ float2 upk2(unsigned long long v) {
    float2 r;
    asm("mov.b64 {%0, %1}, %2;" : "=f"(r.x), "=f"(r.y) : "l"(v));
    return r;
}
__device__ __forceinline__ unsigned long long fma2(unsigned long long a,
                                                   unsigned long long b,
                                                   unsigned long long c) {
    unsigned long long d;
    asm("fma.rn.f32x2 %0, %1, %2, %3;" : "=l"(d) : "l"(a), "l"(b), "l"(c));
    return d;
}
__device__ __forceinline__ unsigned long long mul2(unsigned long long a,
                                                   unsigned long long b) {
    unsigned long long d;
    asm("mul.rn.f32x2 %0, %1, %2;" : "=l"(d) : "l"(a), "l"(b));
    return d;
}

__device__ __forceinline__ uint32_t tf32_rn(float x) {
    uint32_t r;
    asm("cvt.rna.tf32.f32 %0, %1;" : "=r"(r) : "f"(x));
    return r;
}

// ===========================================================================
// tf32 mma.sync GEMM: C[M,N] = A[M,K] @ B[N,K]^T + bias[N], optional ReLU.
// CTA tile 128x128x32, 256 threads, 8 warps (2 M x 4 N), warp tile 64x32.
// Double-buffered SMEM, register-staged global loads with RN tf32 convert.
// Requires M%128==0, N%128==0, K%32==0.
// ===========================================================================
#define BMt 128
#define BNt 128
#define BKt 32
#define TSTRIDE 36                       // floats per row: (36g mod 32)=4g -> conflict-free
#define STAGE_FLOATS (2 * BMt * TSTRIDE) // A tile + B tile per stage (128*36 each)
#define GEMM_SMEM (2 * STAGE_FLOATS * 4) // 73728 bytes

template<bool RELU>
__global__ __launch_bounds__(256, 1)
void gemm_mma(const float* __restrict__ A, const float* __restrict__ B,
              const float* __restrict__ bias, float* __restrict__ C,
              int M, int N, int K)
{
    extern __shared__ float sm[];

    const int tid  = threadIdx.x;
    const int wid  = tid >> 5;
    const int lane = tid & 31;
    const int g    = lane >> 2;   // groupID (0..7)
    const int t    = lane & 3;    // threadID_in_group (0..3)
    const int bm = blockIdx.y * BMt;
    const int bn = blockIdx.x * BNt;
    const int warpM = (wid & 1) * 64;   // 2 warps along M
    const int warpN = (wid >> 1) * 32;  // 4 warps along N

    // accumulators: 4 M-tiles x 4 N-tiles x 4 regs
    float c[4][4][4];
#pragma unroll
    for (int mt = 0; mt < 4; mt++)
#pragma unroll
        for (int nt = 0; nt < 4; nt++)
#pragma unroll
            for (int j = 0; j < 4; j++) c[mt][nt][j] = 0.f;

    const int r_ld  = tid >> 3;   // 0..31 step base row (per 256-thread chunk covers 32 rows? no:)
    // loading map: idx = tid + i*256, row = idx>>3 (0..127), c4 = idx&7 (col/4)
    const int nk = K / BKt;

    float4 ra[4], rb[4];
    // prologue load tile 0
#pragma unroll
    for (int i = 0; i < 4; i++) {
        int idx = tid + i * 256;
        int r = idx >> 3, c4 = idx & 7;
        ra[i] = *(const float4*)(A + (size_t)(bm + r) * K + c4 * 4);
        rb[i] = *(const float4*)(B + (size_t)(bn + r) * K + c4 * 4);
    }
    {
        float* As0 = sm;
        float* Bs0 = sm + BMt * TSTRIDE;
#pragma unroll
        for (int i = 0; i < 4; i++) {
            int idx = tid + i * 256;
            int r = idx >> 3, c4 = idx & 7;
            uint4 ta = { tf32_rn(ra[i].x), tf32_rn(ra[i].y), tf32_rn(ra[i].z), tf32_rn(ra[i].w) };
            uint4 tb = { tf32_rn(rb[i].x), tf32_rn(rb[i].y), tf32_rn(rb[i].z), tf32_rn(rb[i].w) };
            *(uint4*)&As0[r * TSTRIDE + c4 * 4] = ta;
            *(uint4*)&Bs0[r * TSTRIDE + c4 * 4] = tb;
        }
    }
    __syncthreads();

    for (int it = 0; it < nk; ++it) {
        const int s = it & 1;
        float* As = sm + s * STAGE_FLOATS;
        float* Bs = As + BMt * TSTRIDE;

        // prefetch next tile into registers
        if (it + 1 < nk) {
            const int k0 = (it + 1) * BKt;
#pragma unroll
            for (int i = 0; i < 4; i++) {
                int idx = tid + i * 256;
                int r = idx >> 3, c4 = idx & 7;
                ra[i] = *(const float4*)(A + (size_t)(bm + r) * K + k0 + c4 * 4);
                rb[i] = *(const float4*)(B + (size_t)(bn + r) * K + k0 + c4 * 4);
            }
        }

        // compute: 4 k-steps of 8
#pragma unroll
        for (int ks = 0; ks < 4; ks++) {
            uint32_t af[4][4], bf[4][2];
#pragma unroll
            for (int mt = 0; mt < 4; mt++) {
                const float* ap = &As[(warpM + mt * 16 + g) * TSTRIDE + ks * 8 + t];
                af[mt][0] = __float_as_uint(ap[0]);
                af[mt][1] = __float_as_uint(ap[8 * TSTRIDE]);
                af[mt][2] = __float_as_uint(ap[4]);
                af[mt][3] = __float_as_uint(ap[8 * TSTRIDE + 4]);
            }
#pragma unroll
            for (int nt = 0; nt < 4; nt++) {
                const float* bp = &Bs[(warpN + nt * 8 + g) * TSTRIDE + ks * 8 + t];
                bf[nt][0] = __float_as_uint(bp[0]);
                bf[nt][1] = __float_as_uint(bp[4]);
            }
#pragma unroll
            for (int mt = 0; mt < 4; mt++)
#pragma unroll
                for (int nt = 0; nt < 4; nt++) {
                    asm volatile(
                        "mma.sync.aligned.m16n8k8.row.col.f32.tf32.tf32.f32 "
                        "{%0, %1, %2, %3}, {%4, %5, %6, %7}, {%8, %9}, "
                        "{%0, %1, %2, %3};"
                        : "+f"(c[mt][nt][0]), "+f"(c[mt][nt][1]),
                          "+f"(c[mt][nt][2]), "+f"(c[mt][nt][3])
                        : "r"(af[mt][0]), "r"(af[mt][1]), "r"(af[mt][2]), "r"(af[mt][3]),
                          "r"(bf[nt][0]), "r"(bf[nt][1]));
                }
        }

        // stage next tile to smem
        if (it + 1 < nk) {
            __syncthreads();
            float* An = sm + (s ^ 1) * STAGE_FLOATS;
            float* Bn = An + BMt * TSTRIDE;
#pragma unroll
            for (int i = 0; i < 4; i++) {
                int idx = tid + i * 256;
                int r = idx >> 3, c4 = idx & 7;
                uint4 ta = { tf32_rn(ra[i].x), tf32_rn(ra[i].y), tf32_rn(ra[i].z), tf32_rn(ra[i].w) };
                uint4 tb = { tf32_rn(rb[i].x), tf32_rn(rb[i].y), tf32_rn(rb[i].z), tf32_rn(rb[i].w) };
                *(uint4*)&An[r * TSTRIDE + c4 * 4] = ta;
                *(uint4*)&Bn[r * TSTRIDE + c4 * 4] = tb;
            }
            __syncthreads();
        }
    }

    // epilogue: bias (+ReLU), float2 stores straight from fragments
#pragma unroll
    for (int nt = 0; nt < 4; nt++) {
        const int col = bn + warpN + nt * 8 + t * 2;
        const float b0 = __ldg(bias + col);
        const float b1 = __ldg(bias + col + 1);
#pragma unroll
        for (int mt = 0; mt < 4; mt++) {
            const int row0 = bm + warpM + mt * 16 + g;
            float2 v0, v1;
            v0.x = c[mt][nt][0] + b0;  v0.y = c[mt][nt][1] + b1;
            v1.x = c[mt][nt][2] + b0;  v1.y = c[mt][nt][3] + b1;
            if (RELU) {
                v0.x = fmaxf(v0.x, 0.f); v0.y = fmaxf(v0.y, 0.f);
                v1.x = fmaxf(v1.x, 0.f); v1.y = fmaxf(v1.y, 0.f);
            }
            *(float2*)(C + (size_t)row0 * N + col)       = v0;
            *(float2*)(C + (size_t)(row0 + 8) * N + col) = v1;
        }
    }
}

// ---------------------------------------------------------------------------
// Flash-attention (fp32, f32x2 packed FMA): one thread per query row.
// grid: (S/128, H, B), block: 128
// ---------------------------------------------------------------------------
__global__ __launch_bounds__(128)
void attn_kernel(const float* __restrict__ Q, const float* __restrict__ Km,
                 const float* __restrict__ Vm, float* __restrict__ O)
{
    const int KT = 32;
    __shared__ __align__(16) float ks[KT][HD];
    __shared__ __align__(16) float vs[KT][HD];

    const int h = blockIdx.y;
    const int b = blockIdx.z;
    const int row = blockIdx.x * 128 + threadIdx.x;
    const float scale = 0.125f;  // 1/sqrt(64)

    const size_t qbase = ((size_t)b * SS + row) * DD + h * HD;

    unsigned long long q2[HD / 2];
#pragma unroll
    for (int i = 0; i < HD / 4; i++) {
        float4 t = *(const float4*)(Q + qbase + i * 4);
        q2[i * 2 + 0] = pk2(t.x * scale, t.y * scale);
        q2[i * 2 + 1] = pk2(t.z * scale, t.w * scale);
    }

    unsigned long long o2[HD / 2];
#pragma unroll
    for (int j = 0; j < HD / 2; j++) o2[j] = 0ull;
    float m = -1e30f, l = 0.f;

    const float* Kb = Km + (size_t)b * SS * DD + h * HD;
    const float* Vb = Vm + (size_t)b * SS * DD + h * HD;

    for (int k0 = 0; k0 < SS; k0 += KT) {
#pragma unroll
        for (int i = 0; i < 4; i++) {
            int idx = threadIdx.x + i * 128;  // 0..511
            int kr  = idx >> 4;
            int c4  = idx & 15;
            *(float4*)&ks[kr][c4*4] = *(const float4*)(Kb + (size_t)(k0+kr) * DD + c4*4);
            *(float4*)&vs[kr][c4*4] = *(const float4*)(Vb + (size_t)(k0+kr) * DD + c4*4);
        }
        __syncthreads();

        float sc[KT];
        float tmax = -1e30f;
#pragma unroll
        for (int kr = 0; kr < KT; kr++) {
            const ulonglong2* kk = (const ulonglong2*)&ks[kr][0];
            unsigned long long a0 = 0ull, a1 = 0ull;
#pragma unroll
            for (int c = 0; c < HD / 4; c++) {
                ulonglong2 kv = kk[c];
                a0 = fma2(q2[2*c],   kv.x, a0);
                a1 = fma2(q2[2*c+1], kv.y, a1);
            }
            float2 f0 = upk2(a0), f1 = upk2(a1);
            float s = (f0.x + f0.y) + (f1.x + f1.y);
            sc[kr] = s;
            tmax = fmaxf(tmax, s);
        }

        if (tmax > m) {
            float alpha = __expf(m - tmax);
            l *= alpha;
            unsigned long long al2 = pk2(alpha, alpha);
#pragma unroll
            for (int j = 0; j < HD / 2; j++) o2[j] = mul2(o2[j], al2);
            m = tmax;
        }

#pragma unroll
        for (int kr = 0; kr < KT; kr++) {
            float p = __expf(sc[kr] - m);
            l += p;
            unsigned long long p2 = pk2(p, p);
            const ulonglong2* vv = (const ulonglong2*)&vs[kr][0];
#pragma unroll
            for (int c = 0; c < HD / 4; c++) {
                ulonglong2 v2 = vv[c];
                o2[2*c]   = fma2(p2, v2.x, o2[2*c]);
                o2[2*c+1] = fma2(p2, v2.y, o2[2*c+1]);
            }
        }
        __syncthreads();
    }

    float inv = 1.f / l;
    float* Op = O + qbase;
#pragma unroll
    for (int i = 0; i < HD / 4; i++) {
        float2 a = upk2(o2[2*i]), bq = upk2(o2[2*i+1]);
        float4 t;
        t.x = a.x * inv; t.y = a.y * inv;
        t.z = bq.x * inv; t.w = bq.y * inv;
        *(float4*)(Op + i * 4) = t;
    }
}

// ---------------------------------------------------------------------------
// Z = (A*attention_scale + attention_bias) * (1 + Mod*gate)
// ---------------------------------------------------------------------------
__global__ void fuse_kernel(const float4* __restrict__ A, const float4* __restrict__ Mod,
                            float4* __restrict__ Z,
                            const float* __restrict__ dop, const float* __restrict__ ser,
                            const float* __restrict__ nor, const float* __restrict__ ace,
                            const float* __restrict__ asc, const float* __restrict__ abi,
                            int n4)
{
    int i = blockIdx.x * blockDim.x + threadIdx.x;
    if (i >= n4) return;
    float gate = 0.25f * (dop[0] + ser[0] + nor[0] + ace[0]);
    float s = asc[0], bb = abi[0];
    float4 a = A[i], md = Mod[i], z;
    z.x = (a.x * s + bb) * (1.f + md.x * gate);
    z.y = (a.y * s + bb) * (1.f + md.y * gate);
    z.z = (a.z * s + bb) * (1.f + md.z * gate);
    z.w = (a.w * s + bb) * (1.f + md.w * gate);
    Z[i] = z;
}

// ---------------------------------------------------------------------------
extern "C" void kernel_launch(void* const* d_in, const int* in_sizes, int n_in,
                              void* d_out, int out_size)
{
    const float* query = (const float*)d_in[0];
    const float* Wq  = (const float*)d_in[1];  const float* bq  = (const float*)d_in[2];
    const float* Wk  = (const float*)d_in[3];  const float* bk  = (const float*)d_in[4];
    const float* Wv  = (const float*)d_in[5];  const float* bv  = (const float*)d_in[6];
    const float* Wo  = (const float*)d_in[7];  const float* bo  = (const float*)d_in[8];
    const float* Wm1 = (const float*)d_in[9];  const float* bm1 = (const float*)d_in[10];
    const float* Wm2 = (const float*)d_in[11]; const float* bm2 = (const float*)d_in[12];
    const float* dop = (const float*)d_in[13];
    const float* ser = (const float*)d_in[14];
    const float* nor = (const float*)d_in[15];
    const float* ace = (const float*)d_in[16];
    const float* asc = (const float*)d_in[17];
    const float* abi = (const float*)d_in[18];
    float* out = (float*)d_out;

    float *Qp, *Kp, *Vp, *Ap, *Hp, *Mp, *Zp;
    cudaGetSymbolAddress((void**)&Qp, g_Q);
    cudaGetSymbolAddress((void**)&Kp, g_K);
    cudaGetSymbolAddress((void**)&Vp, g_V);
    cudaGetSymbolAddress((void**)&Ap, g_A);
    cudaGetSymbolAddress((void**)&Hp, g_Hd);
    cudaGetSymbolAddress((void**)&Mp, g_Mod);
    cudaGetSymbolAddress((void**)&Zp, g_Z);

    cudaFuncSetAttribute(gemm_mma<false>, cudaFuncAttributeMaxDynamicSharedMemorySize, GEMM_SMEM);
    cudaFuncSetAttribute(gemm_mma<true>,  cudaFuncAttributeMaxDynamicSharedMemorySize, GEMM_SMEM);

    dim3 gBig(DD / BNt, MR / BMt);    // 8 x 32
    dim3 gHid(DHID / BNt, MR / BMt);  // 2 x 32

    // QKV projections (tf32 mma.sync)
    gemm_mma<false><<<gBig, 256, GEMM_SMEM>>>(query, Wq, bq, Qp, MR, DD, DD);
    gemm_mma<false><<<gBig, 256, GEMM_SMEM>>>(query, Wk, bk, Kp, MR, DD, DD);
    gemm_mma<false><<<gBig, 256, GEMM_SMEM>>>(query, Wv, bv, Vp, MR, DD, DD);

    // Neuromodulation MLP
    gemm_mma<true ><<<gHid, 256, GEMM_SMEM>>>(query, Wm1, bm1, Hp, MR, DHID, DD);
    gemm_mma<false><<<gBig, 256, GEMM_SMEM>>>(Hp, Wm2, bm2, Mp, MR, DD, DHID);

    // Attention (writes merged [b,s,d])
    attn_kernel<<<dim3(SS / 128, NH, BB), 128>>>(Qp, Kp, Vp, Ap);

    // Gate fuse
    int n4 = MR * DD / 4;
    fuse_kernel<<<(n4 + 255) / 256, 256>>>((const float4*)Ap, (const float4*)Mp,
                                           (float4*)Zp, dop, ser, nor, ace, asc, abi, n4);

    // Output projection
    gemm_mma<false><<<gBig, 256, GEMM_SMEM>>>(Zp, Wo, bo, out, MR, DD, DD);
}

// round 5
// speedup vs baseline: 3.2927x; 2.0703x over previous
#include <cuda_runtime.h>
#include <cstdint>
#include <math.h>

// Problem constants
#define BB 2
#define SS 2048
#define DD 1024
#define NH 16
#define HD 64
#define MR (BB*SS)      // 4096 rows
#define DHID (DD/4)     // 256

// Scratch (device globals; no allocation allowed)
__device__ float g_Q[MR*DD];
__device__ float g_K[MR*DD];
__device__ float g_V[MR*DD];
__device__ float g_Hd[MR*DHID];
__device__ float g_Mod[MR*DD];
__device__ float g_Z[MR*DD];
__device__ float g_qT[MR*DD];          // tf32-rounded query
__device__ float g_WqT[DD*DD];
__device__ float g_WkT[DD*DD];
__device__ float g_WvT[DD*DD];
__device__ float g_WoT[DD*DD];
__device__ float g_Wm1T[DHID*DD];
__device__ float g_Wm2T[DD*DHID];

// ===========================================================================
// PTX helpers
// ===========================================================================
__device__ __forceinline__ uint32_t smem_u32(const void* p) {
    uint32_t a;
    asm("{ .reg .u64 t; cvta.to.shared.u64 t, %1; cvt.u32.u64 %0, t; }"
        : "=r"(a) : "l"(p));
    return a;
}
__device__ __forceinline__ uint32_t tf32_rn(float x) {
    uint32_t r;
    asm("cvt.rna.tf32.f32 %0, %1;" : "=r"(r) : "f"(x));
    return r;
}
__device__ __forceinline__ float tf32f(float x) {
    return __uint_as_float(tf32_rn(x));
}
__device__ __forceinline__ void cp16(uint32_t dst, const float* src) {
    asm volatile("cp.async.cg.shared.global [%0], [%1], 16;"
                 :: "r"(dst), "l"(src) : "memory");
}
#define CP_COMMIT() asm volatile("cp.async.commit_group;" ::: "memory")
#define CP_WAIT(n)  asm volatile("cp.async.wait_group %0;" :: "n"(n) : "memory")

__device__ __forceinline__ void mma8(float* c, const uint32_t* a,
                                     uint32_t b0, uint32_t b1) {
    asm volatile(
        "mma.sync.aligned.m16n8k8.row.col.f32.tf32.tf32.f32 "
        "{%0,%1,%2,%3}, {%4,%5,%6,%7}, {%8,%9}, {%0,%1,%2,%3};"
        : "+f"(c[0]), "+f"(c[1]), "+f"(c[2]), "+f"(c[3])
        : "r"(a[0]), "r"(a[1]), "r"(a[2]), "r"(a[3]), "r"(b0), "r"(b1));
}

// ===========================================================================
// tf32 round kernel (pre-convert inputs once)
// ===========================================================================
__global__ void round_tf32_kernel(const float4* __restrict__ in,
                                  float4* __restrict__ out, int n4)
{
    int i = blockIdx.x * blockDim.x + threadIdx.x;
    if (i >= n4) return;
    float4 v = in[i];
    float4 r;
    r.x = tf32f(v.x); r.y = tf32f(v.y); r.z = tf32f(v.z); r.w = tf32f(v.w);
    out[i] = r;
}

// ===========================================================================
// tf32 mma GEMM with cp.async 4-stage pipeline.
// C[M,N] = A[M,K] @ B[N,K]^T + bias[N].  A,B already tf32-valued.
// CTA 128x128x32, 256 threads, 8 warps (2M x 4N), warp tile 64x32.
// ===========================================================================
#define BMt 128
#define BNt 128
#define BKt 32
#define TS  36                       // padded row stride (floats); 144B, 16B-aligned
#define STG 4
#define STAGE_F (2 * BMt * TS)       // 9216 floats per stage
#define GEMM_SMEM (STG * STAGE_F * 4)  // 147456 bytes

template<bool RELU, bool ROUND>
__global__ __launch_bounds__(256, 1)
void gemm_cp(const float* __restrict__ A, const float* __restrict__ B,
             const float* __restrict__ bias, float* __restrict__ C,
             int M, int N, int K)
{
    extern __shared__ float sm[];
    const uint32_t sb = smem_u32(sm);

    const int tid  = threadIdx.x;
    const int wid  = tid >> 5;
    const int lane = tid & 31;
    const int g    = lane >> 2;
    const int t    = lane & 3;
    const int bm = blockIdx.y * BMt;
    const int bn = blockIdx.x * BNt;
    const int warpM = (wid & 1) * 64;
    const int warpN = (wid >> 1) * 32;

    float c[4][4][4];
#pragma unroll
    for (int mt = 0; mt < 4; mt++)
#pragma unroll
        for (int nt = 0; nt < 4; nt++)
#pragma unroll
            for (int j = 0; j < 4; j++) c[mt][nt][j] = 0.f;

    const int nk = K / BKt;

    // cp.async stage issue: 1024 A-chunks + 1024 B-chunks of 16B, 8/thread
    auto issue = [&](int it) {
        const int st = it & 3;
        const uint32_t abase = sb + st * STAGE_F * 4;
        const uint32_t bbase = abase + BMt * TS * 4;
        const int k0 = it * BKt;
#pragma unroll
        for (int i = 0; i < 4; i++) {
            int idx = tid + i * 256;
            int r = idx >> 3, ch = idx & 7;
            cp16(abase + (r * TS + ch * 4) * 4, A + (size_t)(bm + r) * K + k0 + ch * 4);
            cp16(bbase + (r * TS + ch * 4) * 4, B + (size_t)(bn + r) * K + k0 + ch * 4);
        }
    };

#pragma unroll
    for (int s = 0; s < 3; s++) {
        if (s < nk) issue(s);
        CP_COMMIT();
    }

    for (int it = 0; it < nk; ++it) {
        CP_WAIT(2);
        __syncthreads();
        if (it + 3 < nk) issue(it + 3);
        CP_COMMIT();

        const float* As = sm + (it & 3) * STAGE_F;
        const float* Bs = As + BMt * TS;

#pragma unroll
        for (int ks = 0; ks < 4; ks++) {
            uint32_t af[4][4], bf[4][2];
#pragma unroll
            for (int mt = 0; mt < 4; mt++) {
                const float* ap = &As[(warpM + mt * 16 + g) * TS + ks * 8 + t];
                af[mt][0] = __float_as_uint(ap[0]);
                af[mt][1] = __float_as_uint(ap[8 * TS]);
                af[mt][2] = __float_as_uint(ap[4]);
                af[mt][3] = __float_as_uint(ap[8 * TS + 4]);
            }
#pragma unroll
            for (int nt = 0; nt < 4; nt++) {
                const float* bp = &Bs[(warpN + nt * 8 + g) * TS + ks * 8 + t];
                bf[nt][0] = __float_as_uint(bp[0]);
                bf[nt][1] = __float_as_uint(bp[4]);
            }
#pragma unroll
            for (int mt = 0; mt < 4; mt++)
#pragma unroll
                for (int nt = 0; nt < 4; nt++)
                    mma8(c[mt][nt], af[mt], bf[nt][0], bf[nt][1]);
        }
    }

    // epilogue
#pragma unroll
    for (int nt = 0; nt < 4; nt++) {
        const int col = bn + warpN + nt * 8 + t * 2;
        const float b0 = __ldg(bias + col);
        const float b1 = __ldg(bias + col + 1);
#pragma unroll
        for (int mt = 0; mt < 4; mt++) {
            const int row0 = bm + warpM + mt * 16 + g;
            float2 v0, v1;
            v0.x = c[mt][nt][0] + b0;  v0.y = c[mt][nt][1] + b1;
            v1.x = c[mt][nt][2] + b0;  v1.y = c[mt][nt][3] + b1;
            if (RELU) {
                v0.x = fmaxf(v0.x, 0.f); v0.y = fmaxf(v0.y, 0.f);
                v1.x = fmaxf(v1.x, 0.f); v1.y = fmaxf(v1.y, 0.f);
            }
            if (ROUND) {
                v0.x = tf32f(v0.x); v0.y = tf32f(v0.y);
                v1.x = tf32f(v1.x); v1.y = tf32f(v1.y);
            }
            *(float2*)(C + (size_t)row0 * N + col)       = v0;
            *(float2*)(C + (size_t)(row0 + 8) * N + col) = v1;
        }
    }
}

// ===========================================================================
// Flash attention via tf32 mma.sync, fused neuromod epilogue.
// CTA: 128 q-rows, loops 32 key-tiles of 64. 8 warps, warp owns 16 q-rows.
// Q/K/V tf32-valued fp32 in merged [b,s,D] layout (head slice of 64).
// Writes Z = (attn*asc+abi)*(1+Mod*gate), tf32-rounded.
// SMEM rows (stride APAD): [0,128) Q, [128,256) K bufs 0/1, [256,384) V bufs
// 0/1, [384,512) P.
// ===========================================================================
#define APAD 72
#define ATT_SMEM (512 * APAD * 4)   // 147456 bytes

__global__ __launch_bounds__(256, 1)
void attn_mma(const float* __restrict__ Q, const float* __restrict__ K,
              const float* __restrict__ V, const float* __restrict__ Mod,
              float* __restrict__ Z,
              const float* __restrict__ dop, const float* __restrict__ ser,
              const float* __restrict__ nor, const float* __restrict__ ace,
              const float* __restrict__ asc, const float* __restrict__ abi)
{
    extern __shared__ float sm[];
    const uint32_t sb = smem_u32(sm);

    const int tid  = threadIdx.x;
    const int wid  = tid >> 5;
    const int lane = tid & 31;
    const int g    = lane >> 2;
    const int t    = lane & 3;
    const int h = blockIdx.y;
    const int b = blockIdx.z;
    const int q0 = blockIdx.x * 128;

    float* sQ = sm;                                // [128][APAD]
    float* sP = sm + 384 * APAD;                   // [128][APAD]

    const float* Qg = Q + ((size_t)(b * SS + q0)) * DD + h * HD;
    const float* Kg = K + ((size_t)b * SS) * DD + h * HD;
    const float* Vg = V + ((size_t)b * SS) * DD + h * HD;

    auto kvload = [&](int tile, int buf) {
        const float* kp = Kg + (size_t)tile * 64 * DD;
        const float* vp = Vg + (size_t)tile * 64 * DD;
        const uint32_t kb = sb + (uint32_t)(128 + buf * 64) * APAD * 4;
        const uint32_t vb = sb + (uint32_t)(256 + buf * 64) * APAD * 4;
#pragma unroll
        for (int i = 0; i < 4; i++) {
            int idx = tid + i * 256;
            int r = idx >> 4, cch = idx & 15;
            cp16(kb + (uint32_t)(r * APAD + cch * 4) * 4, kp + (size_t)r * DD + cch * 4);
            cp16(vb + (uint32_t)(r * APAD + cch * 4) * 4, vp + (size_t)r * DD + cch * 4);
        }
    };

    // Q: 128 rows x 16 chunks = 2048, 8/thread
#pragma unroll
    for (int i = 0; i < 8; i++) {
        int idx = tid + i * 256;
        int r = idx >> 4, cch = idx & 15;
        cp16(sb + (uint32_t)(r * APAD + cch * 4) * 4, Qg + (size_t)r * DD + cch * 4);
    }
    CP_COMMIT();
    kvload(0, 0);
    CP_COMMIT();

    CP_WAIT(1);            // Q ready (KV0 may be pending)
    __syncthreads();

    // cache Q fragments, scale by 1/sqrt(HD)=0.125 (exact under tf32)
    uint32_t aq[8][4];
    {
        const int r0 = wid * 16 + g;
#pragma unroll
        for (int ks = 0; ks < 8; ks++) {
            aq[ks][0] = __float_as_uint(sQ[r0 * APAD + ks * 8 + t] * 0.125f);
            aq[ks][1] = __float_as_uint(sQ[(r0 + 8) * APAD + ks * 8 + t] * 0.125f);
            aq[ks][2] = __float_as_uint(sQ[r0 * APAD + ks * 8 + t + 4] * 0.125f);
            aq[ks][3] = __float_as_uint(sQ[(r0 + 8) * APAD + ks * 8 + t + 4] * 0.125f);
        }
    }

    float oc[8][4];
#pragma unroll
    for (int nt = 0; nt < 8; nt++)
#pragma unroll
        for (int j = 0; j < 4; j++) oc[nt][j] = 0.f;
    float m0 = -1e30f, m1 = -1e30f, l0 = 0.f, l1 = 0.f;

    const int pr = wid * 16 + g;

    for (int kt = 0; kt < 32; kt++) {
        const int s = kt & 1;
        if (kt + 1 < 32) {
            kvload(kt + 1, s ^ 1);
            CP_COMMIT();
            CP_WAIT(1);
        } else {
            CP_WAIT(0);
        }
        __syncthreads();

        const float* sk = sm + (128 + s * 64) * APAD;
        const float* sv = sm + (256 + s * 64) * APAD;

        // S = Q K^T (warp: 16 rows x 64 keys)
        float c[8][4];
#pragma unroll
        for (int nt = 0; nt < 8; nt++)
#pragma unroll
            for (int j = 0; j < 4; j++) c[nt][j] = 0.f;
#pragma unroll
        for (int ks = 0; ks < 8; ks++) {
#pragma unroll
            for (int nt = 0; nt < 8; nt++) {
                uint32_t b0 = __float_as_uint(sk[(nt * 8 + g) * APAD + ks * 8 + t]);
                uint32_t b1 = __float_as_uint(sk[(nt * 8 + g) * APAD + ks * 8 + t + 4]);
                mma8(c[nt], aq[ks], b0, b1);
            }
        }

        // online softmax (rows pr and pr+8; row stats shared across quad)
        float tm0 = -1e30f, tm1 = -1e30f;
#pragma unroll
        for (int nt = 0; nt < 8; nt++) {
            tm0 = fmaxf(tm0, fmaxf(c[nt][0], c[nt][1]));
            tm1 = fmaxf(tm1, fmaxf(c[nt][2], c[nt][3]));
        }
        tm0 = fmaxf(tm0, __shfl_xor_sync(0xffffffffu, tm0, 1));
        tm0 = fmaxf(tm0, __shfl_xor_sync(0xffffffffu, tm0, 2));
        tm1 = fmaxf(tm1, __shfl_xor_sync(0xffffffffu, tm1, 1));
        tm1 = fmaxf(tm1, __shfl_xor_sync(0xffffffffu, tm1, 2));
        const float nm0 = fmaxf(m0, tm0), nm1 = fmaxf(m1, tm1);
        const float a0 = __expf(m0 - nm0), a1 = __expf(m1 - nm1);
        m0 = nm0; m1 = nm1;

        float ls0 = 0.f, ls1 = 0.f;
#pragma unroll
        for (int nt = 0; nt < 8; nt++) {
            float p00 = __expf(c[nt][0] - m0);
            float p01 = __expf(c[nt][1] - m0);
            float p10 = __expf(c[nt][2] - m1);
            float p11 = __expf(c[nt][3] - m1);
            ls0 += p00 + p01;
            ls1 += p10 + p11;
            sP[pr * APAD + nt * 8 + 2 * t]       = tf32f(p00);
            sP[pr * APAD + nt * 8 + 2 * t + 1]   = tf32f(p01);
            sP[(pr + 8) * APAD + nt * 8 + 2 * t]     = tf32f(p10);
            sP[(pr + 8) * APAD + nt * 8 + 2 * t + 1] = tf32f(p11);
        }
        l0 = l0 * a0 + ls0;
        l1 = l1 * a1 + ls1;
#pragma unroll
        for (int nt = 0; nt < 8; nt++) {
            oc[nt][0] *= a0; oc[nt][1] *= a0;
            oc[nt][2] *= a1; oc[nt][3] *= a1;
        }
        __syncwarp();

        // O += P V  (contraction over 64 keys)
#pragma unroll
        for (int ks = 0; ks < 8; ks++) {
            uint32_t ap[4];
            ap[0] = __float_as_uint(sP[pr * APAD + ks * 8 + t]);
            ap[1] = __float_as_uint(sP[(pr + 8) * APAD + ks * 8 + t]);
            ap[2] = __float_as_uint(sP[pr * APAD + ks * 8 + t + 4]);
            ap[3] = __float_as_uint(sP[(pr + 8) * APAD + ks * 8 + t + 4]);
#pragma unroll
            for (int nt = 0; nt < 8; nt++) {
                uint32_t b0 = __float_as_uint(sv[(ks * 8 + t) * APAD + nt * 8 + g]);
                uint32_t b1 = __float_as_uint(sv[(ks * 8 + t + 4) * APAD + nt * 8 + g]);
                mma8(oc[nt], ap, b0, b1);
            }
        }
        __syncthreads();   // protect K/V double buffers
    }

    // reduce l across the quad
    l0 += __shfl_xor_sync(0xffffffffu, l0, 1);
    l0 += __shfl_xor_sync(0xffffffffu, l0, 2);
    l1 += __shfl_xor_sync(0xffffffffu, l1, 1);
    l1 += __shfl_xor_sync(0xffffffffu, l1, 2);
    const float inv0 = 1.f / l0, inv1 = 1.f / l1;

    const float gate = 0.25f * (dop[0] + ser[0] + nor[0] + ace[0]);
    const float scv = asc[0], sbv = abi[0];

    const int r0 = q0 + wid * 16 + g;
#pragma unroll
    for (int nt = 0; nt < 8; nt++) {
        const int col = h * HD + nt * 8 + 2 * t;
        const size_t i0 = ((size_t)(b * SS) + r0) * DD + col;
        float2 md0 = *(const float2*)(Mod + i0);
        float2 md1 = *(const float2*)(Mod + i0 + (size_t)8 * DD);
        float2 z0, z1;
        z0.x = tf32f((oc[nt][0] * inv0 * scv + sbv) * (1.f + md0.x * gate));
        z0.y = tf32f((oc[nt][1] * inv0 * scv + sbv) * (1.f + md0.y * gate));
        z1.x = tf32f((oc[nt][2] * inv1 * scv + sbv) * (1.f + md1.x * gate));
        z1.y = tf32f((oc[nt][3] * inv1 * scv + sbv) * (1.f + md1.y * gate));
        *(float2*)(Z + i0) = z0;
        *(float2*)(Z + i0 + (size_t)8 * DD) = z1;
    }
}

// ---------------------------------------------------------------------------
extern "C" void kernel_launch(void* const* d_in, const int* in_sizes, int n_in,
                              void* d_out, int out_size)
{
    const float* query = (const float*)d_in[0];
    const float* Wq  = (const float*)d_in[1];  const float* bq  = (const float*)d_in[2];
    const float* Wk  = (const float*)d_in[3];  const float* bk  = (const float*)d_in[4];
    const float* Wv  = (const float*)d_in[5];  const float* bv  = (const float*)d_in[6];
    const float* Wo  = (const float*)d_in[7];  const float* bo  = (const float*)d_in[8];
    const float* Wm1 = (const float*)d_in[9];  const float* bm1 = (const float*)d_in[10];
    const float* Wm2 = (const float*)d_in[11]; const float* bm2 = (const float*)d_in[12];
    const float* dop = (const float*)d_in[13];
    const float* ser = (const float*)d_in[14];
    const float* nor = (const float*)d_in[15];
    const float* ace = (const float*)d_in[16];
    const float* asc = (const float*)d_in[17];
    const float* abi = (const float*)d_in[18];
    float* out = (float*)d_out;

    float *Qp, *Kp, *Vp, *Hp, *Mp, *Zp;
    float *qT, *WqT, *WkT, *WvT, *WoT, *Wm1T, *Wm2T;
    cudaGetSymbolAddress((void**)&Qp, g_Q);
    cudaGetSymbolAddress((void**)&Kp, g_K);
    cudaGetSymbolAddress((void**)&Vp, g_V);
    cudaGetSymbolAddress((void**)&Hp, g_Hd);
    cudaGetSymbolAddress((void**)&Mp, g_Mod);
    cudaGetSymbolAddress((void**)&Zp, g_Z);
    cudaGetSymbolAddress((void**)&qT, g_qT);
    cudaGetSymbolAddress((void**)&WqT, g_WqT);
    cudaGetSymbolAddress((void**)&WkT, g_WkT);
    cudaGetSymbolAddress((void**)&WvT, g_WvT);
    cudaGetSymbolAddress((void**)&WoT, g_WoT);
    cudaGetSymbolAddress((void**)&Wm1T, g_Wm1T);
    cudaGetSymbolAddress((void**)&Wm2T, g_Wm2T);

    cudaFuncSetAttribute(gemm_cp<false,true >, cudaFuncAttributeMaxDynamicSharedMemorySize, GEMM_SMEM);
    cudaFuncSetAttribute(gemm_cp<true ,true >, cudaFuncAttributeMaxDynamicSharedMemorySize, GEMM_SMEM);
    cudaFuncSetAttribute(gemm_cp<false,false>, cudaFuncAttributeMaxDynamicSharedMemorySize, GEMM_SMEM);
    cudaFuncSetAttribute(attn_mma, cudaFuncAttributeMaxDynamicSharedMemorySize, ATT_SMEM);

    // pre-round inputs to tf32 values
    auto conv = [&](const float* src, float* dst, int n) {
        int n4 = n / 4;
        round_tf32_kernel<<<(n4 + 255) / 256, 256>>>((const float4*)src, (float4*)dst, n4);
    };
    conv(query, qT, MR * DD);
    conv(Wq, WqT, DD * DD);
    conv(Wk, WkT, DD * DD);
    conv(Wv, WvT, DD * DD);
    conv(Wo, WoT, DD * DD);
    conv(Wm1, Wm1T, DHID * DD);
    conv(Wm2, Wm2T, DD * DHID);

    dim3 gBig(DD / BNt, MR / BMt);    // 8 x 32
    dim3 gHid(DHID / BNt, MR / BMt);  // 2 x 32

    // QKV projections (tf32-rounded outputs feed attention MMA)
    gemm_cp<false,true ><<<gBig, 256, GEMM_SMEM>>>(qT, WqT, bq, Qp, MR, DD, DD);
    gemm_cp<false,true ><<<gBig, 256, GEMM_SMEM>>>(qT, WkT, bk, Kp, MR, DD, DD);
    gemm_cp<false,true ><<<gBig, 256, GEMM_SMEM>>>(qT, WvT, bv, Vp, MR, DD, DD);

    // Neuromodulation MLP (Hd rounded: feeds next GEMM; Mod kept fp32)
    gemm_cp<true ,true ><<<gHid, 256, GEMM_SMEM>>>(qT, Wm1T, bm1, Hp, MR, DHID, DD);
    gemm_cp<false,false><<<gBig, 256, GEMM_SMEM>>>(Hp, Wm2T, bm2, Mp, MR, DD, DHID);

    // Attention with fused neuromod gate epilogue -> Z (tf32-rounded)
    attn_mma<<<dim3(SS / 128, NH, BB), 256, ATT_SMEM>>>(Qp, Kp, Vp, Mp, Zp,
                                                        dop, ser, nor, ace, asc, abi);

    // Output projection
    gemm_cp<false,false><<<gBig, 256, GEMM_SMEM>>>(Zp, WoT, bo, out, MR, DD, DD);
}

// round 6
// speedup vs baseline: 6.8998x; 2.0955x over previous
#include <cuda_runtime.h>
#include <cuda_fp16.h>
#include <cstdint>
#include <math.h>

// Problem constants
#define BB 2
#define SS 2048
#define DD 1024
#define NH 16
#define HD 64
#define MR (BB*SS)      // 4096 rows
#define DHID (DD/4)     // 256

// Scratch (device globals; no allocation allowed)
__device__ __half g_qH[MR*DD];          // fp16 query
__device__ __half g_WqH[DD*DD];
__device__ __half g_WkH[DD*DD];
__device__ __half g_WvH[DD*DD];
__device__ __half g_WoH[DD*DD];
__device__ __half g_Wm1H[DHID*DD];
__device__ __half g_Wm2H[DD*DHID];
__device__ __half g_Q[MR*DD];           // q proj (pre-scaled by 0.125)
__device__ __half g_K[MR*DD];
__device__ __half g_V[MR*DD];
__device__ __half g_Hd[MR*DHID];
__device__ float  g_Mod[MR*DD];
__device__ __half g_Z[MR*DD];

// ===========================================================================
// PTX helpers
// ===========================================================================
__device__ __forceinline__ uint32_t smem_u32(const void* p) {
    uint32_t a;
    asm("{ .reg .u64 t; cvta.to.shared.u64 t, %1; cvt.u32.u64 %0, t; }"
        : "=r"(a) : "l"(p));
    return a;
}
__device__ __forceinline__ void cp16(uint32_t dst, const void* src) {
    asm volatile("cp.async.cg.shared.global [%0], [%1], 16;"
                 :: "r"(dst), "l"(src) : "memory");
}
#define CP_COMMIT() asm volatile("cp.async.commit_group;" ::: "memory")
#define CP_WAIT(n)  asm volatile("cp.async.wait_group %0;" :: "n"(n) : "memory")

__device__ __forceinline__ void mma16(float* c, const uint32_t* a,
                                      uint32_t b0, uint32_t b1) {
    asm volatile(
        "mma.sync.aligned.m16n8k16.row.col.f32.f16.f16.f32 "
        "{%0,%1,%2,%3}, {%4,%5,%6,%7}, {%8,%9}, {%0,%1,%2,%3};"
        : "+f"(c[0]), "+f"(c[1]), "+f"(c[2]), "+f"(c[3])
        : "r"(a[0]), "r"(a[1]), "r"(a[2]), "r"(a[3]), "r"(b0), "r"(b1));
}
__device__ __forceinline__ void ldsm4t(uint32_t& r0, uint32_t& r1,
                                       uint32_t& r2, uint32_t& r3, uint32_t a) {
    asm volatile(
        "ldmatrix.sync.aligned.m8n8.x4.trans.shared.b16 {%0,%1,%2,%3}, [%4];"
        : "=r"(r0), "=r"(r1), "=r"(r2), "=r"(r3) : "r"(a));
}
__device__ __forceinline__ uint32_t h2u(float x, float y) {
    __half2 h = __floats2half2_rn(x, y);
    return *(uint32_t*)&h;
}

// ===========================================================================
// Fused f32 -> f16 conversion for query + 6 weights (one launch)
// ===========================================================================
#define N4_Q   (MR*DD/4)     // 1048576
#define N4_W   (DD*DD/4)     // 262144
#define N4_M   (DHID*DD/4)   // 65536
#define N4_TOT (N4_Q + 4*N4_W + 2*N4_M)

__global__ void convert_all(const float4* __restrict__ q,
                            const float4* __restrict__ wq, const float4* __restrict__ wk,
                            const float4* __restrict__ wv, const float4* __restrict__ wo,
                            const float4* __restrict__ w1, const float4* __restrict__ w2)
{
    int i = blockIdx.x * blockDim.x + threadIdx.x;
    if (i >= N4_TOT) return;
    const float4* s; __half2* d; int off;
    __half2 *dq = (__half2*)g_qH, *dwq = (__half2*)g_WqH, *dwk = (__half2*)g_WkH,
            *dwv = (__half2*)g_WvH, *dwo = (__half2*)g_WoH,
            *d1 = (__half2*)g_Wm1H, *d2 = (__half2*)g_Wm2H;
    if      (i < N4_Q)               { s = q;  d = dq;  off = i; }
    else if (i < N4_Q +   N4_W)      { s = wq; d = dwq; off = i - N4_Q; }
    else if (i < N4_Q + 2*N4_W)      { s = wk; d = dwk; off = i - N4_Q - N4_W; }
    else if (i < N4_Q + 3*N4_W)      { s = wv; d = dwv; off = i - N4_Q - 2*N4_W; }
    else if (i < N4_Q + 4*N4_W)      { s = wo; d = dwo; off = i - N4_Q - 3*N4_W; }
    else if (i < N4_Q + 4*N4_W + N4_M) { s = w1; d = d1; off = i - N4_Q - 4*N4_W; }
    else                             { s = w2; d = d2; off = i - N4_Q - 4*N4_W - N4_M; }
    float4 v = s[off];
    d[2*off]   = __floats2half2_rn(v.x, v.y);
    d[2*off+1] = __floats2half2_rn(v.z, v.w);
}

// ===========================================================================
// fp16 mma GEMM body: C[M,N] = (A[M,K] @ B[N,K]^T + bias) * oscale
// CTA 128x128x32, 256 threads, 8 warps (2M x 4N), 4-stage cp.async.
// ===========================================================================
#define HSTR 40                       // halfs per smem row (80B; conflict-free)
#define STAGE_H (2 * 128 * HSTR)      // 10240 halfs per stage
#define GEMM_SMEM_H (4 * STAGE_H * 2) // 81920 bytes

template<bool RELU, typename CT>
__device__ __forceinline__
void gemm_body(const __half* __restrict__ A, const __half* __restrict__ B,
               const float* __restrict__ bias, CT* __restrict__ C,
               int N, int K, float oscale, int bm, int bn, __half* smh)
{
    const uint32_t sb = smem_u32(smh);
    const int tid  = threadIdx.x;
    const int wid  = tid >> 5;
    const int lane = tid & 31;
    const int g    = lane >> 2;
    const int t    = lane & 3;
    const int warpM = (wid & 1) * 64;
    const int warpN = (wid >> 1) * 32;

    float c[4][4][4];
#pragma unroll
    for (int mt = 0; mt < 4; mt++)
#pragma unroll
        for (int nt = 0; nt < 4; nt++)
#pragma unroll
            for (int j = 0; j < 4; j++) c[mt][nt][j] = 0.f;

    const int nk = K >> 5;

    auto issue = [&](int it) {
        const int st = it & 3;
        const int k0 = it << 5;
#pragma unroll
        for (int i = 0; i < 4; i++) {
            int idx = tid + i * 256;          // 0..1023
            int isB = idx >> 9;
            int j = idx & 511;
            int r = j >> 2, ch = j & 3;       // 128 rows x 4 chunks (8 halfs)
            const __half* src = (isB ? B + (size_t)(bn + r) * K
                                     : A + (size_t)(bm + r) * K) + k0 + ch * 8;
            cp16(sb + (uint32_t)(st * STAGE_H + isB * 128 * HSTR + r * HSTR + ch * 8) * 2, src);
        }
    };

#pragma unroll
    for (int s = 0; s < 3; s++) {
        if (s < nk) issue(s);
        CP_COMMIT();
    }

    for (int it = 0; it < nk; ++it) {
        CP_WAIT(2);
        __syncthreads();
        if (it + 3 < nk) issue(it + 3);
        CP_COMMIT();

        const __half* As = smh + (it & 3) * STAGE_H;
        const __half* Bs = As + 128 * HSTR;

#pragma unroll
        for (int ks = 0; ks < 2; ks++) {
            uint32_t af[4][4], bf[4][2];
#pragma unroll
            for (int mt = 0; mt < 4; mt++) {
                const __half* ap = &As[(warpM + mt * 16 + g) * HSTR + ks * 16 + 2 * t];
                af[mt][0] = *(const uint32_t*)ap;
                af[mt][1] = *(const uint32_t*)(ap + 8 * HSTR);
                af[mt][2] = *(const uint32_t*)(ap + 8);
                af[mt][3] = *(const uint32_t*)(ap + 8 * HSTR + 8);
            }
#pragma unroll
            for (int nt = 0; nt < 4; nt++) {
                const __half* bp = &Bs[(warpN + nt * 8 + g) * HSTR + ks * 16 + 2 * t];
                bf[nt][0] = *(const uint32_t*)bp;
                bf[nt][1] = *(const uint32_t*)(bp + 8);
            }
#pragma unroll
            for (int mt = 0; mt < 4; mt++)
#pragma unroll
                for (int nt = 0; nt < 4; nt++)
                    mma16(c[mt][nt], af[mt], bf[nt][0], bf[nt][1]);
        }
    }

    // epilogue
#pragma unroll
    for (int nt = 0; nt < 4; nt++) {
        const int col = bn + warpN + nt * 8 + t * 2;
        const float b0 = __ldg(bias + col);
        const float b1 = __ldg(bias + col + 1);
#pragma unroll
        for (int mt = 0; mt < 4; mt++) {
            const int row0 = bm + warpM + mt * 16 + g;
            float v00 = (c[mt][nt][0] + b0) * oscale;
            float v01 = (c[mt][nt][1] + b1) * oscale;
            float v10 = (c[mt][nt][2] + b0) * oscale;
            float v11 = (c[mt][nt][3] + b1) * oscale;
            if (RELU) {
                v00 = fmaxf(v00, 0.f); v01 = fmaxf(v01, 0.f);
                v10 = fmaxf(v10, 0.f); v11 = fmaxf(v11, 0.f);
            }
            if (sizeof(CT) == 2) {
                *(uint32_t*)((__half*)C + (size_t)row0 * N + col)       = h2u(v00, v01);
                *(uint32_t*)((__half*)C + (size_t)(row0 + 8) * N + col) = h2u(v10, v11);
            } else {
                *(float2*)((float*)C + (size_t)row0 * N + col)       = make_float2(v00, v01);
                *(float2*)((float*)C + (size_t)(row0 + 8) * N + col) = make_float2(v10, v11);
            }
        }
    }
}

// merged QKV: grid (8, 32, 3)
__global__ __launch_bounds__(256, 2)
void qkv_h(const __half* __restrict__ A,
           const __half* __restrict__ Wq, const __half* __restrict__ Wk,
           const __half* __restrict__ Wv,
           const float* __restrict__ bq, const float* __restrict__ bk,
           const float* __restrict__ bv)
{
    extern __shared__ __half smh[];
    const int z = blockIdx.z;
    const __half* B   = (z == 0) ? Wq : (z == 1) ? Wk : Wv;
    const float* bias = (z == 0) ? bq : (z == 1) ? bk : bv;
    __half* C         = (z == 0) ? g_Q : (z == 1) ? g_K : g_V;
    const float oscale = (z == 0) ? 0.125f : 1.0f;   // fold 1/sqrt(HD) into q
    gemm_body<false, __half>(A, B, bias, C, DD, DD, oscale,
                             blockIdx.y * 128, blockIdx.x * 128, smh);
}

template<bool RELU, typename CT>
__global__ __launch_bounds__(256, 2)
void gemm_h(const __half* __restrict__ A, const __half* __restrict__ B,
            const float* __restrict__ bias, CT* __restrict__ C, int N, int K)
{
    extern __shared__ __half smh[];
    gemm_body<RELU, CT>(A, B, bias, C, N, K, 1.0f,
                        blockIdx.y * 128, blockIdx.x * 128, smh);
}

// ===========================================================================
// fp16 flash attention, fused neuromod epilogue.
// CTA: 128 q-rows x full 2048-key loop (tiles of 64), 8 warps.
// SMEM rows (stride 72 halfs): Q [0,128), K bufs [128,256), V bufs [256,384),
// P [384,512).  73728 bytes -> 2 CTAs/SM.
// ===========================================================================
#define ASTR 72
#define ATT_SMEM (512 * ASTR * 2)

__global__ __launch_bounds__(256, 2)
void attn_h(const __half* __restrict__ Q, const __half* __restrict__ K,
            const __half* __restrict__ V, const float* __restrict__ Mod,
            __half* __restrict__ Z,
            const float* __restrict__ dop, const float* __restrict__ ser,
            const float* __restrict__ nor, const float* __restrict__ ace,
            const float* __restrict__ asc, const float* __restrict__ abi)
{
    extern __shared__ __half smh[];
    const uint32_t sb = smem_u32(smh);

    const int tid  = threadIdx.x;
    const int wid  = tid >> 5;
    const int lane = tid & 31;
    const int g    = lane >> 2;
    const int t    = lane & 3;
    const int h = blockIdx.y;
    const int b = blockIdx.z;
    const int q0 = blockIdx.x * 128;

    __half* sQ = smh;
    __half* sP = smh + 384 * ASTR;

    const __half* Qg = Q + ((size_t)(b * SS + q0)) * DD + h * HD;
    const __half* Kg = K + ((size_t)b * SS) * DD + h * HD;
    const __half* Vg = V + ((size_t)b * SS) * DD + h * HD;

    auto kvload = [&](int tile, int buf) {
        const __half* kp = Kg + (size_t)tile * 64 * DD;
        const __half* vp = Vg + (size_t)tile * 64 * DD;
#pragma unroll
        for (int i = 0; i < 4; i++) {
            int idx = tid + i * 256;          // 0..1023
            int isV = idx >> 9;
            int j = idx & 511;
            int r = j >> 3, ch = j & 7;       // 64 rows x 8 chunks (8 halfs)
            const __half* src = (isV ? vp : kp) + (size_t)r * DD + ch * 8;
            uint32_t dst = sb + (uint32_t)((128 + isV * 128 + buf * 64 + r) * ASTR + ch * 8) * 2;
            cp16(dst, src);
        }
    };

    // Q: 128 rows x 8 chunks
#pragma unroll
    for (int i = 0; i < 4; i++) {
        int idx = tid + i * 256;
        int r = idx >> 3, ch = idx & 7;
        cp16(sb + (uint32_t)(r * ASTR + ch * 8) * 2, Qg + (size_t)r * DD + ch * 8);
    }
    CP_COMMIT();
    kvload(0, 0);
    CP_COMMIT();

    CP_WAIT(1);
    __syncthreads();

    // cache Q fragments (Q already scaled by 0.125 in projection)
    const int r0 = wid * 16 + g;
    uint32_t aq[4][4];
#pragma unroll
    for (int ks = 0; ks < 4; ks++) {
        const __half* ap = &sQ[r0 * ASTR + ks * 16 + 2 * t];
        aq[ks][0] = *(const uint32_t*)ap;
        aq[ks][1] = *(const uint32_t*)(ap + 8 * ASTR);
        aq[ks][2] = *(const uint32_t*)(ap + 8);
        aq[ks][3] = *(const uint32_t*)(ap + 8 * ASTR + 8);
    }

    float oc[8][4];
#pragma unroll
    for (int nt = 0; nt < 8; nt++)
#pragma unroll
        for (int j = 0; j < 4; j++) oc[nt][j] = 0.f;
    float m0 = -1e30f, m1 = -1e30f, l0 = 0.f, l1 = 0.f;

    const int pr = r0;

    for (int kt = 0; kt < 32; kt++) {
        const int s = kt & 1;
        if (kt + 1 < 32) {
            kvload(kt + 1, s ^ 1);
            CP_COMMIT();
            CP_WAIT(1);
        } else {
            CP_WAIT(0);
        }
        __syncthreads();

        const __half* sk = smh + (128 + s * 64) * ASTR;
        const uint32_t svb = sb + (uint32_t)(256 + s * 64) * ASTR * 2;

        // S = Q K^T
        float c[8][4];
#pragma unroll
        for (int nt = 0; nt < 8; nt++)
#pragma unroll
            for (int j = 0; j < 4; j++) c[nt][j] = 0.f;
#pragma unroll
        for (int ks = 0; ks < 4; ks++) {
#pragma unroll
            for (int nt = 0; nt < 8; nt++) {
                const __half* bp = &sk[(nt * 8 + g) * ASTR + ks * 16 + 2 * t];
                mma16(c[nt], aq[ks], *(const uint32_t*)bp, *(const uint32_t*)(bp + 8));
            }
        }

        // online softmax (rows pr / pr+8; stats shared across quad)
        float tm0 = -1e30f, tm1 = -1e30f;
#pragma unroll
        for (int nt = 0; nt < 8; nt++) {
            tm0 = fmaxf(tm0, fmaxf(c[nt][0], c[nt][1]));
            tm1 = fmaxf(tm1, fmaxf(c[nt][2], c[nt][3]));
        }
        tm0 = fmaxf(tm0, __shfl_xor_sync(0xffffffffu, tm0, 1));
        tm0 = fmaxf(tm0, __shfl_xor_sync(0xffffffffu, tm0, 2));
        tm1 = fmaxf(tm1, __shfl_xor_sync(0xffffffffu, tm1, 1));
        tm1 = fmaxf(tm1, __shfl_xor_sync(0xffffffffu, tm1, 2));
        const float nm0 = fmaxf(m0, tm0), nm1 = fmaxf(m1, tm1);
        const float a0 = __expf(m0 - nm0), a1 = __expf(m1 - nm1);
        m0 = nm0; m1 = nm1;

        float ls0 = 0.f, ls1 = 0.f;
#pragma unroll
        for (int nt = 0; nt < 8; nt++) {
            float p00 = __expf(c[nt][0] - m0);
            float p01 = __expf(c[nt][1] - m0);
            float p10 = __expf(c[nt][2] - m1);
            float p11 = __expf(c[nt][3] - m1);
            ls0 += p00 + p01;
            ls1 += p10 + p11;
            *(uint32_t*)&sP[pr * ASTR + nt * 8 + 2 * t]       = h2u(p00, p01);
            *(uint32_t*)&sP[(pr + 8) * ASTR + nt * 8 + 2 * t] = h2u(p10, p11);
        }
        l0 = l0 * a0 + ls0;
        l1 = l1 * a1 + ls1;
#pragma unroll
        for (int nt = 0; nt < 8; nt++) {
            oc[nt][0] *= a0; oc[nt][1] *= a0;
            oc[nt][2] *= a1; oc[nt][3] *= a1;
        }
        __syncwarp();

        // O += P V ; V B-fragments via ldmatrix.x4.trans
        const int lrow = (lane & 7) + ((lane >> 3) & 1) * 8;
        const int lcol = ((lane >> 4) & 1) * 8;
#pragma unroll
        for (int ks = 0; ks < 4; ks++) {
            uint32_t ap[4];
            const __half* pp = &sP[pr * ASTR + ks * 16 + 2 * t];
            ap[0] = *(const uint32_t*)pp;
            ap[1] = *(const uint32_t*)(pp + 8 * ASTR);
            ap[2] = *(const uint32_t*)(pp + 8);
            ap[3] = *(const uint32_t*)(pp + 8 * ASTR + 8);
#pragma unroll
            for (int p = 0; p < 4; p++) {
                uint32_t v0, v1, v2, v3;
                uint32_t addr = svb + (uint32_t)((ks * 16 + lrow) * ASTR + p * 16 + lcol) * 2;
                ldsm4t(v0, v1, v2, v3, addr);
                mma16(oc[2*p],     ap, v0, v1);
                mma16(oc[2*p + 1], ap, v2, v3);
            }
        }
        __syncthreads();   // protect K/V double buffers
    }

    // reduce l across the quad
    l0 += __shfl_xor_sync(0xffffffffu, l0, 1);
    l0 += __shfl_xor_sync(0xffffffffu, l0, 2);
    l1 += __shfl_xor_sync(0xffffffffu, l1, 1);
    l1 += __shfl_xor_sync(0xffffffffu, l1, 2);
    const float inv0 = 1.f / l0, inv1 = 1.f / l1;

    const float gate = 0.25f * (dop[0] + ser[0] + nor[0] + ace[0]);
    const float scv = asc[0], sbv = abi[0];

    const int rg = q0 + r0;
#pragma unroll
    for (int nt = 0; nt < 8; nt++) {
        const int col = h * HD + nt * 8 + 2 * t;
        const size_t i0 = ((size_t)(b * SS) + rg) * DD + col;
        float2 md0 = *(const float2*)(Mod + i0);
        float2 md1 = *(const float2*)(Mod + i0 + (size_t)8 * DD);
        float z00 = (oc[nt][0] * inv0 * scv + sbv) * (1.f + md0.x * gate);
        float z01 = (oc[nt][1] * inv0 * scv + sbv) * (1.f + md0.y * gate);
        float z10 = (oc[nt][2] * inv1 * scv + sbv) * (1.f + md1.x * gate);
        float z11 = (oc[nt][3] * inv1 * scv + sbv) * (1.f + md1.y * gate);
        *(uint32_t*)&Z[i0]                  = h2u(z00, z01);
        *(uint32_t*)&Z[i0 + (size_t)8 * DD] = h2u(z10, z11);
    }
}

// ---------------------------------------------------------------------------
extern "C" void kernel_launch(void* const* d_in, const int* in_sizes, int n_in,
                              void* d_out, int out_size)
{
    const float* query = (const float*)d_in[0];
    const float* Wq  = (const float*)d_in[1];  const float* bq  = (const float*)d_in[2];
    const float* Wk  = (const float*)d_in[3];  const float* bk  = (const float*)d_in[4];
    const float* Wv  = (const float*)d_in[5];  const float* bv  = (const float*)d_in[6];
    const float* Wo  = (const float*)d_in[7];  const float* bo  = (const float*)d_in[8];
    const float* Wm1 = (const float*)d_in[9];  const float* bm1 = (const float*)d_in[10];
    const float* Wm2 = (const float*)d_in[11]; const float* bm2 = (const float*)d_in[12];
    const float* dop = (const float*)d_in[13];
    const float* ser = (const float*)d_in[14];
    const float* nor = (const float*)d_in[15];
    const float* ace = (const float*)d_in[16];
    const float* asc = (const float*)d_in[17];
    const float* abi = (const float*)d_in[18];
    float* out = (float*)d_out;

    __half *qH, *WqH, *WkH, *WvH, *WoH, *Wm1H, *Wm2H;
    __half *Qp, *Kp, *Vp, *Hp, *Zp;
    float *Mp;
    cudaGetSymbolAddress((void**)&qH,  g_qH);
    cudaGetSymbolAddress((void**)&WqH, g_WqH);
    cudaGetSymbolAddress((void**)&WkH, g_WkH);
    cudaGetSymbolAddress((void**)&WvH, g_WvH);
    cudaGetSymbolAddress((void**)&WoH, g_WoH);
    cudaGetSymbolAddress((void**)&Wm1H, g_Wm1H);
    cudaGetSymbolAddress((void**)&Wm2H, g_Wm2H);
    cudaGetSymbolAddress((void**)&Qp, g_Q);
    cudaGetSymbolAddress((void**)&Kp, g_K);
    cudaGetSymbolAddress((void**)&Vp, g_V);
    cudaGetSymbolAddress((void**)&Hp, g_Hd);
    cudaGetSymbolAddress((void**)&Mp, g_Mod);
    cudaGetSymbolAddress((void**)&Zp, g_Z);

    cudaFuncSetAttribute(qkv_h, cudaFuncAttributeMaxDynamicSharedMemorySize, GEMM_SMEM_H);
    cudaFuncSetAttribute(gemm_h<true , __half>, cudaFuncAttributeMaxDynamicSharedMemorySize, GEMM_SMEM_H);
    cudaFuncSetAttribute(gemm_h<false, float >, cudaFuncAttributeMaxDynamicSharedMemorySize, GEMM_SMEM_H);
    cudaFuncSetAttribute(attn_h, cudaFuncAttributeMaxDynamicSharedMemorySize, ATT_SMEM);

    // 1. convert inputs to fp16 (one launch)
    convert_all<<<(N4_TOT + 255) / 256, 256>>>(
        (const float4*)query, (const float4*)Wq, (const float4*)Wk,
        (const float4*)Wv, (const float4*)Wo, (const float4*)Wm1, (const float4*)Wm2);

    // 2. merged QKV projections
    qkv_h<<<dim3(DD / 128, MR / 128, 3), 256, GEMM_SMEM_H>>>(qH, WqH, WkH, WvH, bq, bk, bv);

    // 3. neuromodulation MLP
    gemm_h<true , __half><<<dim3(DHID / 128, MR / 128), 256, GEMM_SMEM_H>>>(qH, Wm1H, bm1, Hp, DHID, DD);
    gemm_h<false, float ><<<dim3(DD / 128, MR / 128), 256, GEMM_SMEM_H>>>(Hp, Wm2H, bm2, Mp, DD, DHID);

    // 4. attention with fused gate epilogue -> Z (fp16)
    attn_h<<<dim3(SS / 128, NH, BB), 256, ATT_SMEM>>>(Qp, Kp, Vp, Mp, Zp,
                                                      dop, ser, nor, ace, asc, abi);

    // 5. output projection (fp32 out)
    gemm_h<false, float ><<<dim3(DD / 128, MR / 128), 256, GEMM_SMEM_H>>>(Zp, WoH, bo, out, DD, DD);
}

// round 7
// speedup vs baseline: 7.5537x; 1.0948x over previous
#include <cuda_runtime.h>
#include <cuda_fp16.h>
#include <cstdint>
#include <math.h>

// Problem constants
#define BB 2
#define SS 2048
#define DD 1024
#define NH 16
#define HD 64
#define MR (BB*SS)      // 4096 rows
#define DHID (DD/4)     // 256

// Scratch (device globals; no allocation allowed)
__device__ __half g_qH[MR*DD];          // fp16 query
__device__ __half g_WqH[DD*DD];
__device__ __half g_WkH[DD*DD];
__device__ __half g_WvH[DD*DD];
__device__ __half g_WoH[DD*DD];
__device__ __half g_Wm1H[DHID*DD];
__device__ __half g_Wm2H[DD*DHID];
__device__ __half g_Q[MR*DD];           // q proj (pre-scaled by 0.125*log2e)
__device__ __half g_K[MR*DD];
__device__ __half g_V[MR*DD];
__device__ __half g_Hd[MR*DHID];
__device__ float  g_Mod[MR*DD];
__device__ __half g_Z[MR*DD];

// ===========================================================================
// PTX helpers
// ===========================================================================
__device__ __forceinline__ uint32_t smem_u32(const void* p) {
    uint32_t a;
    asm("{ .reg .u64 t; cvta.to.shared.u64 t, %1; cvt.u32.u64 %0, t; }"
        : "=r"(a) : "l"(p));
    return a;
}
__device__ __forceinline__ void cp16(uint32_t dst, const void* src) {
    asm volatile("cp.async.cg.shared.global [%0], [%1], 16;"
                 :: "r"(dst), "l"(src) : "memory");
}
#define CP_COMMIT() asm volatile("cp.async.commit_group;" ::: "memory")
#define CP_WAIT(n)  asm volatile("cp.async.wait_group %0;" :: "n"(n) : "memory")

__device__ __forceinline__ void mma16(float* c, const uint32_t* a,
                                      uint32_t b0, uint32_t b1) {
    asm volatile(
        "mma.sync.aligned.m16n8k16.row.col.f32.f16.f16.f32 "
        "{%0,%1,%2,%3}, {%4,%5,%6,%7}, {%8,%9}, {%0,%1,%2,%3};"
        : "+f"(c[0]), "+f"(c[1]), "+f"(c[2]), "+f"(c[3])
        : "r"(a[0]), "r"(a[1]), "r"(a[2]), "r"(a[3]), "r"(b0), "r"(b1));
}
__device__ __forceinline__ void ldsm4(uint32_t& r0, uint32_t& r1,
                                      uint32_t& r2, uint32_t& r3, uint32_t a) {
    asm volatile(
        "ldmatrix.sync.aligned.m8n8.x4.shared.b16 {%0,%1,%2,%3}, [%4];"
        : "=r"(r0), "=r"(r1), "=r"(r2), "=r"(r3) : "r"(a));
}
__device__ __forceinline__ void ldsm4t(uint32_t& r0, uint32_t& r1,
                                       uint32_t& r2, uint32_t& r3, uint32_t a) {
    asm volatile(
        "ldmatrix.sync.aligned.m8n8.x4.trans.shared.b16 {%0,%1,%2,%3}, [%4];"
        : "=r"(r0), "=r"(r1), "=r"(r2), "=r"(r3) : "r"(a));
}
__device__ __forceinline__ uint32_t h2u(float x, float y) {
    __half2 h = __floats2half2_rn(x, y);
    return *(uint32_t*)&h;
}
__device__ __forceinline__ float ex2f(float x) {
    float y;
    asm("ex2.approx.f32 %0, %1;" : "=f"(y) : "f"(x));
    return y;
}
__device__ __forceinline__ uint32_t ex2h2(uint32_t x) {
    uint32_t y;
    asm("ex2.approx.f16x2 %0, %1;" : "=r"(y) : "r"(x));
    return y;
}

// ===========================================================================
// Fused f32 -> f16 conversion for query + 6 weights (one launch)
// ===========================================================================
#define N4_Q   (MR*DD/4)
#define N4_W   (DD*DD/4)
#define N4_M   (DHID*DD/4)
#define N4_TOT (N4_Q + 4*N4_W + 2*N4_M)

__global__ void convert_all(const float4* __restrict__ q,
                            const float4* __restrict__ wq, const float4* __restrict__ wk,
                            const float4* __restrict__ wv, const float4* __restrict__ wo,
                            const float4* __restrict__ w1, const float4* __restrict__ w2)
{
    int i = blockIdx.x * blockDim.x + threadIdx.x;
    if (i >= N4_TOT) return;
    const float4* s; __half2* d; int off;
    __half2 *dq = (__half2*)g_qH, *dwq = (__half2*)g_WqH, *dwk = (__half2*)g_WkH,
            *dwv = (__half2*)g_WvH, *dwo = (__half2*)g_WoH,
            *d1 = (__half2*)g_Wm1H, *d2 = (__half2*)g_Wm2H;
    if      (i < N4_Q)               { s = q;  d = dq;  off = i; }
    else if (i < N4_Q +   N4_W)      { s = wq; d = dwq; off = i - N4_Q; }
    else if (i < N4_Q + 2*N4_W)      { s = wk; d = dwk; off = i - N4_Q - N4_W; }
    else if (i < N4_Q + 3*N4_W)      { s = wv; d = dwv; off = i - N4_Q - 2*N4_W; }
    else if (i < N4_Q + 4*N4_W)      { s = wo; d = dwo; off = i - N4_Q - 3*N4_W; }
    else if (i < N4_Q + 4*N4_W + N4_M) { s = w1; d = d1; off = i - N4_Q - 4*N4_W; }
    else                             { s = w2; d = d2; off = i - N4_Q - 4*N4_W - N4_M; }
    float4 v = s[off];
    d[2*off]   = __floats2half2_rn(v.x, v.y);
    d[2*off+1] = __floats2half2_rn(v.z, v.w);
}

// ===========================================================================
// fp16 mma GEMM body (unchanged from R6, passing)
// ===========================================================================
#define HSTR 40
#define STAGE_H (2 * 128 * HSTR)
#define GEMM_SMEM_H (4 * STAGE_H * 2)

template<bool RELU, typename CT>
__device__ __forceinline__
void gemm_body(const __half* __restrict__ A, const __half* __restrict__ B,
               const float* __restrict__ bias, CT* __restrict__ C,
               int N, int K, float oscale, int bm, int bn, __half* smh)
{
    const uint32_t sb = smem_u32(smh);
    const int tid  = threadIdx.x;
    const int wid  = tid >> 5;
    const int lane = tid & 31;
    const int g    = lane >> 2;
    const int t    = lane & 3;
    const int warpM = (wid & 1) * 64;
    const int warpN = (wid >> 1) * 32;

    float c[4][4][4];
#pragma unroll
    for (int mt = 0; mt < 4; mt++)
#pragma unroll
        for (int nt = 0; nt < 4; nt++)
#pragma unroll
            for (int j = 0; j < 4; j++) c[mt][nt][j] = 0.f;

    const int nk = K >> 5;

    auto issue = [&](int it) {
        const int st = it & 3;
        const int k0 = it << 5;
#pragma unroll
        for (int i = 0; i < 4; i++) {
            int idx = tid + i * 256;
            int isB = idx >> 9;
            int j = idx & 511;
            int r = j >> 2, ch = j & 3;
            const __half* src = (isB ? B + (size_t)(bn + r) * K
                                     : A + (size_t)(bm + r) * K) + k0 + ch * 8;
            cp16(sb + (uint32_t)(st * STAGE_H + isB * 128 * HSTR + r * HSTR + ch * 8) * 2, src);
        }
    };

#pragma unroll
    for (int s = 0; s < 3; s++) {
        if (s < nk) issue(s);
        CP_COMMIT();
    }

    for (int it = 0; it < nk; ++it) {
        CP_WAIT(2);
        __syncthreads();
        if (it + 3 < nk) issue(it + 3);
        CP_COMMIT();

        const __half* As = smh + (it & 3) * STAGE_H;
        const __half* Bs = As + 128 * HSTR;

#pragma unroll
        for (int ks = 0; ks < 2; ks++) {
            uint32_t af[4][4], bf[4][2];
#pragma unroll
            for (int mt = 0; mt < 4; mt++) {
                const __half* ap = &As[(warpM + mt * 16 + g) * HSTR + ks * 16 + 2 * t];
                af[mt][0] = *(const uint32_t*)ap;
                af[mt][1] = *(const uint32_t*)(ap + 8 * HSTR);
                af[mt][2] = *(const uint32_t*)(ap + 8);
                af[mt][3] = *(const uint32_t*)(ap + 8 * HSTR + 8);
            }
#pragma unroll
            for (int nt = 0; nt < 4; nt++) {
                const __half* bp = &Bs[(warpN + nt * 8 + g) * HSTR + ks * 16 + 2 * t];
                bf[nt][0] = *(const uint32_t*)bp;
                bf[nt][1] = *(const uint32_t*)(bp + 8);
            }
#pragma unroll
            for (int mt = 0; mt < 4; mt++)
#pragma unroll
                for (int nt = 0; nt < 4; nt++)
                    mma16(c[mt][nt], af[mt], bf[nt][0], bf[nt][1]);
        }
    }

#pragma unroll
    for (int nt = 0; nt < 4; nt++) {
        const int col = bn + warpN + nt * 8 + t * 2;
        const float b0 = __ldg(bias + col);
        const float b1 = __ldg(bias + col + 1);
#pragma unroll
        for (int mt = 0; mt < 4; mt++) {
            const int row0 = bm + warpM + mt * 16 + g;
            float v00 = (c[mt][nt][0] + b0) * oscale;
            float v01 = (c[mt][nt][1] + b1) * oscale;
            float v10 = (c[mt][nt][2] + b0) * oscale;
            float v11 = (c[mt][nt][3] + b1) * oscale;
            if (RELU) {
                v00 = fmaxf(v00, 0.f); v01 = fmaxf(v01, 0.f);
                v10 = fmaxf(v10, 0.f); v11 = fmaxf(v11, 0.f);
            }
            if (sizeof(CT) == 2) {
                *(uint32_t*)((__half*)C + (size_t)row0 * N + col)       = h2u(v00, v01);
                *(uint32_t*)((__half*)C + (size_t)(row0 + 8) * N + col) = h2u(v10, v11);
            } else {
                *(float2*)((float*)C + (size_t)row0 * N + col)       = make_float2(v00, v01);
                *(float2*)((float*)C + (size_t)(row0 + 8) * N + col) = make_float2(v10, v11);
            }
        }
    }
}

// merged QKV: grid (8, 32, 3).  Q pre-scaled by 0.125*log2(e) for base-2 softmax.
#define QSCALE (0.125f * 1.4426950408889634f)

__global__ __launch_bounds__(256, 2)
void qkv_h(const __half* __restrict__ A,
           const __half* __restrict__ Wq, const __half* __restrict__ Wk,
           const __half* __restrict__ Wv,
           const float* __restrict__ bq, const float* __restrict__ bk,
           const float* __restrict__ bv)
{
    extern __shared__ __half smh[];
    const int z = blockIdx.z;
    const __half* B   = (z == 0) ? Wq : (z == 1) ? Wk : Wv;
    const float* bias = (z == 0) ? bq : (z == 1) ? bk : bv;
    __half* C         = (z == 0) ? g_Q : (z == 1) ? g_K : g_V;
    const float oscale = (z == 0) ? QSCALE : 1.0f;
    gemm_body<false, __half>(A, B, bias, C, DD, DD, oscale,
                             blockIdx.y * 128, blockIdx.x * 128, smh);
}

template<bool RELU, typename CT>
__global__ __launch_bounds__(256, 2)
void gemm_h(const __half* __restrict__ A, const __half* __restrict__ B,
            const float* __restrict__ bias, CT* __restrict__ C, int N, int K)
{
    extern __shared__ __half smh[];
    gemm_body<RELU, CT>(A, B, bias, C, N, K, 1.0f,
                        blockIdx.y * 128, blockIdx.x * 128, smh);
}

// ===========================================================================
// fp16 flash attention v2: register-resident P, base-2 f16x2 softmax,
// ldmatrix K fragments, 4-buffer KV ring with 1 syncthreads/iter.
// SMEM rows (stride 72 halfs): Q [0,128), K ring [128,384), V ring [384,640).
// 92160 bytes -> 2 CTAs/SM.
// ===========================================================================
#define ASTR 72
#define ATT_SMEM (640 * ASTR * 2)

__global__ __launch_bounds__(256, 2)
void attn_h(const __half* __restrict__ Q, const __half* __restrict__ K,
            const __half* __restrict__ V, const float* __restrict__ Mod,
            __half* __restrict__ Z,
            const float* __restrict__ dop, const float* __restrict__ ser,
            const float* __restrict__ nor, const float* __restrict__ ace,
            const float* __restrict__ asc, const float* __restrict__ abi)
{
    extern __shared__ __half smh[];
    const uint32_t sb = smem_u32(smh);

    const int tid  = threadIdx.x;
    const int wid  = tid >> 5;
    const int lane = tid & 31;
    const int g    = lane >> 2;
    const int t    = lane & 3;
    const int h = blockIdx.y;
    const int b = blockIdx.z;
    const int q0 = blockIdx.x * 128;

    const __half* Qg = Q + ((size_t)(b * SS + q0)) * DD + h * HD;
    const __half* Kg = K + ((size_t)b * SS) * DD + h * HD;
    const __half* Vg = V + ((size_t)b * SS) * DD + h * HD;

    auto kvload = [&](int tile, int buf) {
        const __half* kp = Kg + (size_t)tile * 64 * DD;
        const __half* vp = Vg + (size_t)tile * 64 * DD;
#pragma unroll
        for (int i = 0; i < 4; i++) {
            int idx = tid + i * 256;          // 0..1023
            int isV = idx >> 9;
            int j = idx & 511;
            int r = j >> 3, ch = j & 7;       // 64 rows x 8 chunks (8 halfs)
            const __half* src = (isV ? vp : kp) + (size_t)r * DD + ch * 8;
            uint32_t dst = sb + (uint32_t)((128 + isV * 256 + buf * 64 + r) * ASTR + ch * 8) * 2;
            cp16(dst, src);
        }
    };

    // Q: 128 rows x 8 chunks
#pragma unroll
    for (int i = 0; i < 4; i++) {
        int idx = tid + i * 256;
        int r = idx >> 3, ch = idx & 7;
        cp16(sb + (uint32_t)(r * ASTR + ch * 8) * 2, Qg + (size_t)r * DD + ch * 8);
    }
    CP_COMMIT();                       // G0 = Q
    kvload(0, 0); CP_COMMIT();         // G1
    kvload(1, 1); CP_COMMIT();         // G2
    kvload(2, 2); CP_COMMIT();         // G3

    CP_WAIT(3);
    __syncthreads();                   // Q visible everywhere

    // cache Q fragments (Q already scaled by 0.125*log2e)
    const int r0 = wid * 16 + g;
    uint32_t aq[4][4];
#pragma unroll
    for (int ks = 0; ks < 4; ks++) {
        const __half* ap = &smh[r0 * ASTR + ks * 16 + 2 * t];
        aq[ks][0] = *(const uint32_t*)ap;
        aq[ks][1] = *(const uint32_t*)(ap + 8 * ASTR);
        aq[ks][2] = *(const uint32_t*)(ap + 8);
        aq[ks][3] = *(const uint32_t*)(ap + 8 * ASTR + 8);
    }

    float oc[8][4];
#pragma unroll
    for (int nt = 0; nt < 8; nt++)
#pragma unroll
        for (int j = 0; j < 4; j++) oc[nt][j] = 0.f;
    float m0 = -1e30f, m1 = -1e30f, l0 = 0.f, l1 = 0.f;

    // ldmatrix lane addressing
    const int krow  = ((lane >> 4) & 1) * 8 + (lane & 7);   // K (non-trans)
    const int kfeat = ((lane >> 3) & 1) * 8;
    const int vrow  = (lane & 7) + ((lane >> 3) & 1) * 8;   // V (trans)
    const int vcol  = ((lane >> 4) & 1) * 8;

    for (int kt = 0; kt < 32; kt++) {
        // drain so that kv(kt) [group G(kt+1)] is complete; two newest pending
        CP_WAIT(2);
        __syncthreads();               // visibility + ring write-after-read
        if (kt + 3 < 32) kvload(kt + 3, (kt + 3) & 3);
        CP_COMMIT();                   // keep group arithmetic uniform (may be empty)

        const uint32_t skb = sb + (uint32_t)(128 + (kt & 3) * 64) * ASTR * 2;
        const uint32_t svb = sb + (uint32_t)(384 + (kt & 3) * 64) * ASTR * 2;

        // S = Q K^T : K fragments via ldmatrix.x4
        float c[8][4];
#pragma unroll
        for (int nt = 0; nt < 8; nt++)
#pragma unroll
            for (int j = 0; j < 4; j++) c[nt][j] = 0.f;
#pragma unroll
        for (int ks = 0; ks < 4; ks++) {
#pragma unroll
            for (int qp = 0; qp < 4; qp++) {
                uint32_t b0, b1, b2, b3;
                uint32_t addr = skb + (uint32_t)((qp * 16 + krow) * ASTR + ks * 16 + kfeat) * 2;
                ldsm4(b0, b1, b2, b3, addr);
                mma16(c[2*qp],     aq[ks], b0, b1);
                mma16(c[2*qp + 1], aq[ks], b2, b3);
            }
        }

        // online softmax, base-2 domain
        float tm0 = -1e30f, tm1 = -1e30f;
#pragma unroll
        for (int nt = 0; nt < 8; nt++) {
            tm0 = fmaxf(tm0, fmaxf(c[nt][0], c[nt][1]));
            tm1 = fmaxf(tm1, fmaxf(c[nt][2], c[nt][3]));
        }
        tm0 = fmaxf(tm0, __shfl_xor_sync(0xffffffffu, tm0, 1));
        tm0 = fmaxf(tm0, __shfl_xor_sync(0xffffffffu, tm0, 2));
        tm1 = fmaxf(tm1, __shfl_xor_sync(0xffffffffu, tm1, 1));
        tm1 = fmaxf(tm1, __shfl_xor_sync(0xffffffffu, tm1, 2));
        const float nm0 = fmaxf(m0, tm0), nm1 = fmaxf(m1, tm1);
        const float a0 = ex2f(m0 - nm0), a1 = ex2f(m1 - nm1);
        m0 = nm0; m1 = nm1;

        // P fragments directly in registers (identity with mma A-fragment layout)
        uint32_t pf[8][2];
        float ls0 = 0.f, ls1 = 0.f;
#pragma unroll
        for (int nt = 0; nt < 8; nt++) {
            uint32_t x0 = h2u(c[nt][0] - m0, c[nt][1] - m0);
            uint32_t x1 = h2u(c[nt][2] - m1, c[nt][3] - m1);
            uint32_t p0 = ex2h2(x0);
            uint32_t p1 = ex2h2(x1);
            pf[nt][0] = p0;
            pf[nt][1] = p1;
            float2 f0 = __half22float2(*(__half2*)&p0);
            float2 f1 = __half22float2(*(__half2*)&p1);
            ls0 += f0.x + f0.y;
            ls1 += f1.x + f1.y;
        }
        l0 = l0 * a0 + ls0;
        l1 = l1 * a1 + ls1;
#pragma unroll
        for (int nt = 0; nt < 8; nt++) {
            oc[nt][0] *= a0; oc[nt][1] *= a0;
            oc[nt][2] *= a1; oc[nt][3] *= a1;
        }

        // O += P V : V B-fragments via ldmatrix.x4.trans
#pragma unroll
        for (int ks = 0; ks < 4; ks++) {
            uint32_t ap[4];
            ap[0] = pf[2*ks][0];
            ap[1] = pf[2*ks][1];
            ap[2] = pf[2*ks + 1][0];
            ap[3] = pf[2*ks + 1][1];
#pragma unroll
            for (int p = 0; p < 4; p++) {
                uint32_t v0, v1, v2, v3;
                uint32_t addr = svb + (uint32_t)((ks * 16 + vrow) * ASTR + p * 16 + vcol) * 2;
                ldsm4t(v0, v1, v2, v3, addr);
                mma16(oc[2*p],     ap, v0, v1);
                mma16(oc[2*p + 1], ap, v2, v3);
            }
        }
    }

    // reduce l across the quad
    l0 += __shfl_xor_sync(0xffffffffu, l0, 1);
    l0 += __shfl_xor_sync(0xffffffffu, l0, 2);
    l1 += __shfl_xor_sync(0xffffffffu, l1, 1);
    l1 += __shfl_xor_sync(0xffffffffu, l1, 2);
    const float inv0 = 1.f / l0, inv1 = 1.f / l1;

    const float gate = 0.25f * (dop[0] + ser[0] + nor[0] + ace[0]);
    const float scv = asc[0], sbv = abi[0];

    const int rg = q0 + r0;
#pragma unroll
    for (int nt = 0; nt < 8; nt++) {
        const int col = h * HD + nt * 8 + 2 * t;
        const size_t i0 = ((size_t)(b * SS) + rg) * DD + col;
        float2 md0 = *(const float2*)(Mod + i0);
        float2 md1 = *(const float2*)(Mod + i0 + (size_t)8 * DD);
        float z00 = (oc[nt][0] * inv0 * scv + sbv) * (1.f + md0.x * gate);
        float z01 = (oc[nt][1] * inv0 * scv + sbv) * (1.f + md0.y * gate);
        float z10 = (oc[nt][2] * inv1 * scv + sbv) * (1.f + md1.x * gate);
        float z11 = (oc[nt][3] * inv1 * scv + sbv) * (1.f + md1.y * gate);
        *(uint32_t*)&Z[i0]                  = h2u(z00, z01);
        *(uint32_t*)&Z[i0 + (size_t)8 * DD] = h2u(z10, z11);
    }
}

// ---------------------------------------------------------------------------
extern "C" void kernel_launch(void* const* d_in, const int* in_sizes, int n_in,
                              void* d_out, int out_size)
{
    const float* query = (const float*)d_in[0];
    const float* Wq  = (const float*)d_in[1];  const float* bq  = (const float*)d_in[2];
    const float* Wk  = (const float*)d_in[3];  const float* bk  = (const float*)d_in[4];
    const float* Wv  = (const float*)d_in[5];  const float* bv  = (const float*)d_in[6];
    const float* Wo  = (const float*)d_in[7];  const float* bo  = (const float*)d_in[8];
    const float* Wm1 = (const float*)d_in[9];  const float* bm1 = (const float*)d_in[10];
    const float* Wm2 = (const float*)d_in[11]; const float* bm2 = (const float*)d_in[12];
    const float* dop = (const float*)d_in[13];
    const float* ser = (const float*)d_in[14];
    const float* nor = (const float*)d_in[15];
    const float* ace = (const float*)d_in[16];
    const float* asc = (const float*)d_in[17];
    const float* abi = (const float*)d_in[18];
    float* out = (float*)d_out;

    __half *qH, *WqH, *WkH, *WvH, *WoH, *Wm1H, *Wm2H;
    __half *Qp, *Kp, *Vp, *Hp, *Zp;
    float *Mp;
    cudaGetSymbolAddress((void**)&qH,  g_qH);
    cudaGetSymbolAddress((void**)&WqH, g_WqH);
    cudaGetSymbolAddress((void**)&WkH, g_WkH);
    cudaGetSymbolAddress((void**)&WvH, g_WvH);
    cudaGetSymbolAddress((void**)&WoH, g_WoH);
    cudaGetSymbolAddress((void**)&Wm1H, g_Wm1H);
    cudaGetSymbolAddress((void**)&Wm2H, g_Wm2H);
    cudaGetSymbolAddress((void**)&Qp, g_Q);
    cudaGetSymbolAddress((void**)&Kp, g_K);
    cudaGetSymbolAddress((void**)&Vp, g_V);
    cudaGetSymbolAddress((void**)&Hp, g_Hd);
    cudaGetSymbolAddress((void**)&Mp, g_Mod);
    cudaGetSymbolAddress((void**)&Zp, g_Z);

    cudaFuncSetAttribute(qkv_h, cudaFuncAttributeMaxDynamicSharedMemorySize, GEMM_SMEM_H);
    cudaFuncSetAttribute(gemm_h<true , __half>, cudaFuncAttributeMaxDynamicSharedMemorySize, GEMM_SMEM_H);
    cudaFuncSetAttribute(gemm_h<false, float >, cudaFuncAttributeMaxDynamicSharedMemorySize, GEMM_SMEM_H);
    cudaFuncSetAttribute(attn_h, cudaFuncAttributeMaxDynamicSharedMemorySize, ATT_SMEM);

    // 1. convert inputs to fp16 (one launch)
    convert_all<<<(N4_TOT + 255) / 256, 256>>>(
        (const float4*)query, (const float4*)Wq, (const float4*)Wk,
        (const float4*)Wv, (const float4*)Wo, (const float4*)Wm1, (const float4*)Wm2);

    // 2. merged QKV projections
    qkv_h<<<dim3(DD / 128, MR / 128, 3), 256, GEMM_SMEM_H>>>(qH, WqH, WkH, WvH, bq, bk, bv);

    // 3. neuromodulation MLP
    gemm_h<true , __half><<<dim3(DHID / 128, MR / 128), 256, GEMM_SMEM_H>>>(qH, Wm1H, bm1, Hp, DHID, DD);
    gemm_h<false, float ><<<dim3(DD / 128, MR / 128), 256, GEMM_SMEM_H>>>(Hp, Wm2H, bm2, Mp, DD, DHID);

    // 4. attention with fused gate epilogue -> Z (fp16)
    attn_h<<<dim3(SS / 128, NH, BB), 256, ATT_SMEM>>>(Qp, Kp, Vp, Mp, Zp,
                                                      dop, ser, nor, ace, asc, abi);

    // 5. output projection (fp32 out)
    gemm_h<false, float ><<<dim3(DD / 128, MR / 128), 256, GEMM_SMEM_H>>>(Zp, WoH, bo, out, DD, DD);
}